// round 1
// baseline (speedup 1.0000x reference)
#include <cuda_runtime.h>

#define BATCH 2
#define SEQL  2048
#define HISTL 2048
#define TTOT  4096
#define NHEAD 16
#define HD    128
#define DIM   2048
#define MROWS 4096   // BATCH*SEQL

// Scratch (device globals: allocation-free contract)
__device__ float g_q[(size_t)MROWS * DIM];
__device__ float g_attn[(size_t)MROWS * DIM];

// ---------------------------------------------------------------------------
// GEMM NT: C[m,n] = sum_k A[m,k] * B[n,k];  M=4096, N=2048, K=2048 (f32)
// mode 0: C row-major [m*DIM + n]
// mode 1: KV remap:   C[((m>>11)*TTOT + HISTL + (m&2047))*DIM + n]
// ---------------------------------------------------------------------------
#define BM 128
#define BN 128
#define BKK 16
#define PADG 4

__global__ __launch_bounds__(256) void gemm_nt_kernel(
    const float* __restrict__ A, const float* __restrict__ Bw,
    float* __restrict__ C, int mode)
{
    __shared__ __align__(16) float As[BKK][BM + PADG];
    __shared__ __align__(16) float Bs[BKK][BN + PADG];

    const int tid = threadIdx.x;
    const int ty = tid >> 4, tx = tid & 15;
    const int bm = blockIdx.y * BM, bn = blockIdx.x * BN;

    float acc[8][8];
#pragma unroll
    for (int i = 0; i < 8; i++)
#pragma unroll
        for (int j = 0; j < 8; j++) acc[i][j] = 0.0f;

    const int lr = tid >> 2;          // 0..63
    const int lc = (tid & 3) * 4;     // 0,4,8,12

    for (int kb = 0; kb < DIM; kb += BKK) {
#pragma unroll
        for (int half = 0; half < 2; half++) {
            const int r = lr + half * 64;
            float4 av = *(const float4*)&A[(size_t)(bm + r) * DIM + kb + lc];
            As[lc + 0][r] = av.x; As[lc + 1][r] = av.y;
            As[lc + 2][r] = av.z; As[lc + 3][r] = av.w;
            float4 bv = *(const float4*)&Bw[(size_t)(bn + r) * DIM + kb + lc];
            Bs[lc + 0][r] = bv.x; Bs[lc + 1][r] = bv.y;
            Bs[lc + 2][r] = bv.z; Bs[lc + 3][r] = bv.w;
        }
        __syncthreads();
#pragma unroll
        for (int k = 0; k < BKK; k++) {
            float4 a0 = *(const float4*)&As[k][ty * 8];
            float4 a1 = *(const float4*)&As[k][ty * 8 + 4];
            float4 b0 = *(const float4*)&Bs[k][tx * 8];
            float4 b1 = *(const float4*)&Bs[k][tx * 8 + 4];
            float av[8] = {a0.x, a0.y, a0.z, a0.w, a1.x, a1.y, a1.z, a1.w};
            float bv[8] = {b0.x, b0.y, b0.z, b0.w, b1.x, b1.y, b1.z, b1.w};
#pragma unroll
            for (int i = 0; i < 8; i++)
#pragma unroll
                for (int j = 0; j < 8; j++) acc[i][j] += av[i] * bv[j];
        }
        __syncthreads();
    }

#pragma unroll
    for (int i = 0; i < 8; i++) {
        const int m = bm + ty * 8 + i;
        size_t rowoff;
        if (mode == 0) {
            rowoff = (size_t)m * DIM;
        } else {
            const int b = m >> 11, s = m & 2047;
            rowoff = ((size_t)b * TTOT + HISTL + s) * DIM;
        }
        float4 o0 = make_float4(acc[i][0], acc[i][1], acc[i][2], acc[i][3]);
        float4 o1 = make_float4(acc[i][4], acc[i][5], acc[i][6], acc[i][7]);
        *(float4*)&C[rowoff + bn + tx * 8]     = o0;
        *(float4*)&C[rowoff + bn + tx * 8 + 4] = o1;
    }
}

// ---------------------------------------------------------------------------
// Flash attention (fp32): per (b,h): O = softmax(Q K^T / sqrt(D) + causal) V
// BQ=64 q-rows per block, BKT=64 keys per tile, online softmax.
// ---------------------------------------------------------------------------
#define BQ 64
#define BKT 64
#define QPAD 132
#define PPAD 65

__global__ __launch_bounds__(256) void attn_kernel(
    const float* __restrict__ q, const float* __restrict__ kall,
    const float* __restrict__ vall, float* __restrict__ outp)
{
    extern __shared__ __align__(16) float sm[];
    float* Qs = sm;                       // [BQ][QPAD]
    float* Ks = sm + BQ * QPAD;           // [BKT][QPAD]
    float* Vs = sm + 2 * BQ * QPAD;       // [BKT][QPAD]
    float* Ps = sm + 3 * BQ * QPAD;       // [BQ][PPAD]

    const int tid = threadIdx.x;
    const int ty = tid >> 4, tx = tid & 15;
    const int qt = blockIdx.x, h = blockIdx.y, b = blockIdx.z;

    // Load Q tile (64 rows x 128)
    for (int li = tid; li < BQ * 32; li += 256) {
        const int r = li >> 5, c = (li & 31) * 4;
        float4 v = *(const float4*)&q[(size_t)(b * SEQL + qt * BQ + r) * DIM + h * HD + c];
        *(float4*)&Qs[r * QPAD + c] = v;
    }

    float m_i[4], l_i[4], O[4][8];
#pragma unroll
    for (int i = 0; i < 4; i++) {
        m_i[i] = -1e30f; l_i[i] = 0.0f;
#pragma unroll
        for (int j = 0; j < 8; j++) O[i][j] = 0.0f;
    }

    const int ntiles = (HISTL / BKT) + qt + 1;
    const float scale = 0.08838834764831845f;  // 1/sqrt(128)

    for (int kt = 0; kt < ntiles; kt++) {
        __syncthreads();  // protect Ks/Vs/Ps from previous iteration
        for (int li = tid; li < BKT * 32; li += 256) {
            const int r = li >> 5, c = (li & 31) * 4;
            const size_t g = (size_t)(b * TTOT + kt * BKT + r) * DIM + h * HD + c;
            *(float4*)&Ks[r * QPAD + c] = *(const float4*)&kall[g];
            *(float4*)&Vs[r * QPAD + c] = *(const float4*)&vall[g];
        }
        __syncthreads();

        // S = Q K^T (4x4 per thread)
        float s[4][4];
#pragma unroll
        for (int i = 0; i < 4; i++)
#pragma unroll
            for (int j = 0; j < 4; j++) s[i][j] = 0.0f;

        for (int d4 = 0; d4 < HD; d4 += 4) {
            float4 qv[4], kv[4];
#pragma unroll
            for (int i = 0; i < 4; i++)
                qv[i] = *(const float4*)&Qs[(ty * 4 + i) * QPAD + d4];
#pragma unroll
            for (int j = 0; j < 4; j++)
                kv[j] = *(const float4*)&Ks[(tx * 4 + j) * QPAD + d4];
#pragma unroll
            for (int i = 0; i < 4; i++)
#pragma unroll
                for (int j = 0; j < 4; j++)
                    s[i][j] += qv[i].x * kv[j].x + qv[i].y * kv[j].y
                             + qv[i].z * kv[j].z + qv[i].w * kv[j].w;
        }

        const bool diag = (kt == ntiles - 1);
#pragma unroll
        for (int i = 0; i < 4; i++)
#pragma unroll
            for (int j = 0; j < 4; j++) {
                float v = s[i][j] * scale;
                if (diag && (tx * 4 + j > ty * 4 + i)) v = -1e30f;
                s[i][j] = v;
            }

        // Online softmax per row (rows shared across the 16 tx lanes = half-warp)
#pragma unroll
        for (int i = 0; i < 4; i++) {
            float mx = fmaxf(fmaxf(s[i][0], s[i][1]), fmaxf(s[i][2], s[i][3]));
#pragma unroll
            for (int off = 8; off; off >>= 1)
                mx = fmaxf(mx, __shfl_xor_sync(0xffffffffu, mx, off));
            const float mnew = fmaxf(m_i[i], mx);
            const float alpha = __expf(m_i[i] - mnew);
            float p0 = __expf(s[i][0] - mnew);
            float p1 = __expf(s[i][1] - mnew);
            float p2 = __expf(s[i][2] - mnew);
            float p3 = __expf(s[i][3] - mnew);
            float sum = p0 + p1 + p2 + p3;
#pragma unroll
            for (int off = 8; off; off >>= 1)
                sum += __shfl_xor_sync(0xffffffffu, sum, off);
            l_i[i] = l_i[i] * alpha + sum;
            m_i[i] = mnew;
#pragma unroll
            for (int j = 0; j < 8; j++) O[i][j] *= alpha;
            float* pr = &Ps[(ty * 4 + i) * PPAD + tx * 4];
            pr[0] = p0; pr[1] = p1; pr[2] = p2; pr[3] = p3;
        }
        __syncthreads();

        // O += P V  (rows ty*4+i, cols tx*8..+7)
        for (int k = 0; k < BKT; k++) {
            float4 v0 = *(const float4*)&Vs[k * QPAD + tx * 8];
            float4 v1 = *(const float4*)&Vs[k * QPAD + tx * 8 + 4];
#pragma unroll
            for (int i = 0; i < 4; i++) {
                const float p = Ps[(ty * 4 + i) * PPAD + k];
                O[i][0] += p * v0.x; O[i][1] += p * v0.y;
                O[i][2] += p * v0.z; O[i][3] += p * v0.w;
                O[i][4] += p * v1.x; O[i][5] += p * v1.y;
                O[i][6] += p * v1.z; O[i][7] += p * v1.w;
            }
        }
    }

#pragma unroll
    for (int i = 0; i < 4; i++) {
        const float inv = 1.0f / l_i[i];
        const size_t g = (size_t)(b * SEQL + qt * BQ + ty * 4 + i) * DIM + h * HD + tx * 8;
        float4 w0 = make_float4(O[i][0] * inv, O[i][1] * inv, O[i][2] * inv, O[i][3] * inv);
        float4 w1 = make_float4(O[i][4] * inv, O[i][5] * inv, O[i][6] * inv, O[i][7] * inv);
        *(float4*)&outp[g]     = w0;
        *(float4*)&outp[g + 4] = w1;
    }
}

// ---------------------------------------------------------------------------
extern "C" void kernel_launch(void* const* d_in, const int* in_sizes, int n_in,
                              void* d_out, int out_size)
{
    const float* x  = (const float*)d_in[0];
    const float* pk = (const float*)d_in[1];
    const float* pv = (const float*)d_in[2];
    // d_in[3] = mask (unused; causal structure applied analytically)
    const float* wq = (const float*)d_in[4];
    const float* wk = (const float*)d_in[5];
    const float* wv = (const float*)d_in[6];
    const float* wo = (const float*)d_in[7];

    float* out  = (float*)d_out;                         // [B,S,DIM]
    float* kall = out  + (size_t)BATCH * SEQL * DIM;     // [B,TTOT,HK,D]
    float* vall = kall + (size_t)BATCH * TTOT * DIM;     // [B,TTOT,HK,D]

    float *qbuf, *abuf;
    cudaGetSymbolAddress((void**)&qbuf, g_q);
    cudaGetSymbolAddress((void**)&abuf, g_attn);

    // History concat: prev_k/prev_v -> k_all/v_all[:, :HISTL]
    for (int b = 0; b < BATCH; b++) {
        cudaMemcpyAsync(kall + (size_t)b * TTOT * DIM, pk + (size_t)b * HISTL * DIM,
                        (size_t)HISTL * DIM * sizeof(float), cudaMemcpyDeviceToDevice, 0);
        cudaMemcpyAsync(vall + (size_t)b * TTOT * DIM, pv + (size_t)b * HISTL * DIM,
                        (size_t)HISTL * DIM * sizeof(float), cudaMemcpyDeviceToDevice, 0);
    }

    dim3 ggrid(DIM / BN, MROWS / BM);
    gemm_nt_kernel<<<ggrid, 256>>>(x, wq, qbuf, 0);   // Q -> scratch
    gemm_nt_kernel<<<ggrid, 256>>>(x, wk, kall, 1);   // K -> k_all[:, HISTL:]
    gemm_nt_kernel<<<ggrid, 256>>>(x, wv, vall, 1);   // V -> v_all[:, HISTL:]

    const size_t smem = (size_t)(3 * BQ * QPAD + BQ * PPAD) * sizeof(float); // 118016 B
    cudaFuncSetAttribute(attn_kernel, cudaFuncAttributeMaxDynamicSharedMemorySize, (int)smem);
    attn_kernel<<<dim3(SEQL / BQ, NHEAD, BATCH), 256, smem>>>(qbuf, kall, vall, abuf);

    gemm_nt_kernel<<<ggrid, 256>>>(abuf, wo, out, 0); // output projection
}

// round 2
// speedup vs baseline: 2.4946x; 2.4946x over previous
#include <cuda_runtime.h>
#include <cstdint>

#define BATCH 2
#define SEQL  2048
#define HISTL 2048
#define TTOT  4096
#define NHEAD 16
#define HD    128
#define DIM   2048
#define MROWS 4096

__device__ float g_q[(size_t)MROWS * DIM];
__device__ float g_attn[(size_t)MROWS * DIM];

__device__ __forceinline__ unsigned f2tf(float x) {
    unsigned u; asm("cvt.rna.tf32.f32 %0, %1;" : "=r"(u) : "f"(x)); return u;
}
__device__ __forceinline__ float f2tff(float x) { return __uint_as_float(f2tf(x)); }

__device__ __forceinline__ void mma8(float* c, const unsigned* a, const unsigned* b) {
    asm volatile("mma.sync.aligned.m16n8k8.row.col.f32.tf32.tf32.f32 "
                 "{%0,%1,%2,%3}, {%4,%5,%6,%7}, {%8,%9}, {%0,%1,%2,%3};"
                 : "+f"(c[0]), "+f"(c[1]), "+f"(c[2]), "+f"(c[3])
                 : "r"(a[0]), "r"(a[1]), "r"(a[2]), "r"(a[3]),
                   "r"(b[0]), "r"(b[1]));
}

// ---------------------------------------------------------------------------
// TF32 GEMM NT: C[m,n] = sum_k A[m,k]*B[n,k]; M=4096,N=2048,K=2048
// mode 0: row-major out; mode 1: KV-concat remap
// ---------------------------------------------------------------------------
#define RS 20   // smem row stride (floats); 20 % 32 == 4 -> conflict-free frag LDS

__global__ __launch_bounds__(256) void gemm_tf32(
    const float* __restrict__ A, const float* __restrict__ Bw,
    float* __restrict__ C, int mode)
{
    __shared__ __align__(16) float As[128 * RS];   // [m][k]
    __shared__ __align__(16) float Bs[128 * RS];   // [n][k]

    const int tid = threadIdx.x, lane = tid & 31, warp = tid >> 5;
    const int g = lane >> 2, t = lane & 3;
    const int wm = (warp >> 2) * 64;   // warp row offset (0,64)
    const int wn = (warp & 3) * 32;    // warp col offset (0..96)
    const int bm = blockIdx.y * 128, bn = blockIdx.x * 128;
    const int lr = tid >> 1, lc = (tid & 1) * 8;

    const float* Ap = A  + (size_t)(bm + lr) * DIM + lc;
    const float* Bp = Bw + (size_t)(bn + lr) * DIM + lc;

    float acc[4][4][4];
#pragma unroll
    for (int i = 0; i < 4; i++)
#pragma unroll
        for (int j = 0; j < 4; j++)
#pragma unroll
            for (int c = 0; c < 4; c++) acc[i][j][c] = 0.0f;

    float4 pa0 = *(const float4*)(Ap),     pa1 = *(const float4*)(Ap + 4);
    float4 pb0 = *(const float4*)(Bp),     pb1 = *(const float4*)(Bp + 4);

    const unsigned* Asu = (const unsigned*)As;
    const unsigned* Bsu = (const unsigned*)Bs;

    // store helper (tf32-rounded)
#define STORE_TILE(a0,a1,b0,b1) do { \
    *(float4*)&As[lr*RS+lc]   = make_float4(f2tff((a0).x),f2tff((a0).y),f2tff((a0).z),f2tff((a0).w)); \
    *(float4*)&As[lr*RS+lc+4] = make_float4(f2tff((a1).x),f2tff((a1).y),f2tff((a1).z),f2tff((a1).w)); \
    *(float4*)&Bs[lr*RS+lc]   = make_float4(f2tff((b0).x),f2tff((b0).y),f2tff((b0).z),f2tff((b0).w)); \
    *(float4*)&Bs[lr*RS+lc+4] = make_float4(f2tff((b1).x),f2tff((b1).y),f2tff((b1).z),f2tff((b1).w)); \
} while (0)

    STORE_TILE(pa0, pa1, pb0, pb1);
    __syncthreads();

    for (int kb = 16; kb <= DIM; kb += 16) {
        if (kb < DIM) {
            pa0 = *(const float4*)(Ap + kb); pa1 = *(const float4*)(Ap + kb + 4);
            pb0 = *(const float4*)(Bp + kb); pb1 = *(const float4*)(Bp + kb + 4);
        }
#pragma unroll
        for (int ks = 0; ks < 16; ks += 8) {
            unsigned af[4][4];
#pragma unroll
            for (int mt = 0; mt < 4; mt++) {
                const int m0 = wm + mt * 16;
                af[mt][0] = Asu[(m0 + g)     * RS + ks + t];
                af[mt][1] = Asu[(m0 + g + 8) * RS + ks + t];
                af[mt][2] = Asu[(m0 + g)     * RS + ks + t + 4];
                af[mt][3] = Asu[(m0 + g + 8) * RS + ks + t + 4];
            }
#pragma unroll
            for (int nt = 0; nt < 4; nt++) {
                const int n0 = wn + nt * 8;
                unsigned bf[2] = { Bsu[(n0 + g) * RS + ks + t],
                                   Bsu[(n0 + g) * RS + ks + t + 4] };
#pragma unroll
                for (int mt = 0; mt < 4; mt++) mma8(acc[mt][nt], af[mt], bf);
            }
        }
        __syncthreads();
        if (kb < DIM) {
            STORE_TILE(pa0, pa1, pb0, pb1);
            __syncthreads();
        }
    }

#pragma unroll
    for (int mt = 0; mt < 4; mt++) {
        const int m0 = bm + wm + mt * 16 + g;
        const int m1 = m0 + 8;
        size_t ro0, ro1;
        if (mode == 0) {
            ro0 = (size_t)m0 * DIM; ro1 = (size_t)m1 * DIM;
        } else {
            ro0 = ((size_t)(m0 >> 11) * TTOT + HISTL + (m0 & 2047)) * DIM;
            ro1 = ((size_t)(m1 >> 11) * TTOT + HISTL + (m1 & 2047)) * DIM;
        }
#pragma unroll
        for (int nt = 0; nt < 4; nt++) {
            const int col = bn + wn + nt * 8 + 2 * t;
            *(float2*)&C[ro0 + col] = make_float2(acc[mt][nt][0], acc[mt][nt][1]);
            *(float2*)&C[ro1 + col] = make_float2(acc[mt][nt][2], acc[mt][nt][3]);
        }
    }
}

// ---------------------------------------------------------------------------
// TF32 flash attention: BQ=64 q rows, BKT=64 kv per tile, online softmax.
// 8 warps: S phase warp = 16q x 32kv (4x2 grid); PV phase warp = 16q x 64d.
// ---------------------------------------------------------------------------
#define QS 132   // Q/K row stride (132 % 32 == 4)
#define VS 136   // V row stride (136 % 32 == 8: conflict-free k-indexed frags)
#define PS 68    // P row stride (68 % 32 == 4)

__global__ __launch_bounds__(256) void attn_tf32(
    const float* __restrict__ q, const float* __restrict__ kall,
    const float* __restrict__ vall, float* __restrict__ outp)
{
    extern __shared__ __align__(16) float sm[];
    float* Qs   = sm;                 // [64][QS]
    float* Ks   = Qs + 64 * QS;       // [64][QS]
    float* Vs   = Ks + 64 * QS;       // [64][VS]
    float* Ps   = Vs + 64 * VS;       // [64][PS]
    float* redM = Ps + 64 * PS;       // [2][64]
    float* redS = redM + 128;         // [2][64]

    const int tid = threadIdx.x, lane = tid & 31, warp = tid >> 5;
    const int g = lane >> 2, t = lane & 3;
    const int qt = blockIdx.x, h = blockIdx.y, b = blockIdx.z;
    const int wq = (warp >> 1) * 16;   // warp q-row offset (0,16,32,48)
    const int wk = warp & 1;           // kv half (S phase) / d half (PV phase)

    // Load Q tile (tf32-rounded)
    for (int li = tid; li < 64 * 32; li += 256) {
        const int r = li >> 5, c = (li & 31) * 4;
        float4 v = *(const float4*)&q[(size_t)(b * SEQL + qt * 64 + r) * DIM + h * HD + c];
        *(float4*)&Qs[r * QS + c] =
            make_float4(f2tff(v.x), f2tff(v.y), f2tff(v.z), f2tff(v.w));
    }

    float O[8][4];
#pragma unroll
    for (int i = 0; i < 8; i++)
#pragma unroll
        for (int c = 0; c < 4; c++) O[i][c] = 0.0f;
    float m0r = -1e30f, m1r = -1e30f, l0 = 0.0f, l1 = 0.0f;

    const int ntiles = HISTL / 64 + qt + 1;
    const float scale = 0.08838834764831845f;

    const unsigned* Qu = (const unsigned*)Qs;
    const unsigned* Ku = (const unsigned*)Ks;
    const unsigned* Vu = (const unsigned*)Vs;
    const unsigned* Pu = (const unsigned*)Ps;

    for (int kt = 0; kt < ntiles; kt++) {
        __syncthreads();
        for (int li = tid; li < 64 * 32; li += 256) {
            const int r = li >> 5, c = (li & 31) * 4;
            const size_t gg = (size_t)(b * TTOT + kt * 64 + r) * DIM + h * HD + c;
            float4 kv4 = *(const float4*)&kall[gg];
            *(float4*)&Ks[r * QS + c] =
                make_float4(f2tff(kv4.x), f2tff(kv4.y), f2tff(kv4.z), f2tff(kv4.w));
            float4 vv4 = *(const float4*)&vall[gg];
            *(float4*)&Vs[r * VS + c] =
                make_float4(f2tff(vv4.x), f2tff(vv4.y), f2tff(vv4.z), f2tff(vv4.w));
        }
        __syncthreads();

        // ---- S = Q K^T (warp: 16q x 32kv) ----
        float s[4][4];
#pragma unroll
        for (int nt = 0; nt < 4; nt++)
#pragma unroll
            for (int c = 0; c < 4; c++) s[nt][c] = 0.0f;

#pragma unroll
        for (int ks = 0; ks < 128; ks += 8) {
            unsigned af[4] = { Qu[(wq + g)     * QS + ks + t],
                               Qu[(wq + g + 8) * QS + ks + t],
                               Qu[(wq + g)     * QS + ks + t + 4],
                               Qu[(wq + g + 8) * QS + ks + t + 4] };
#pragma unroll
            for (int nt = 0; nt < 4; nt++) {
                const int n0 = wk * 32 + nt * 8;
                unsigned bf[2] = { Ku[(n0 + g) * QS + ks + t],
                                   Ku[(n0 + g) * QS + ks + t + 4] };
                mma8(s[nt], af, bf);
            }
        }

        // scale + causal mask on diagonal tile
        const bool diag = (kt == ntiles - 1);
#pragma unroll
        for (int nt = 0; nt < 4; nt++) {
            const int colb = wk * 32 + nt * 8 + 2 * t;
#pragma unroll
            for (int c = 0; c < 4; c++) {
                float v = s[nt][c] * scale;
                const int row = wq + g + ((c >= 2) ? 8 : 0);
                const int col = colb + (c & 1);
                if (diag && col > row) v = -1e30f;
                s[nt][c] = v;
            }
        }

        // row max (local + lane-group + cross-warp via smem)
        float rm0 = -1e30f, rm1 = -1e30f;
#pragma unroll
        for (int nt = 0; nt < 4; nt++) {
            rm0 = fmaxf(rm0, fmaxf(s[nt][0], s[nt][1]));
            rm1 = fmaxf(rm1, fmaxf(s[nt][2], s[nt][3]));
        }
#pragma unroll
        for (int off = 1; off <= 2; off <<= 1) {
            rm0 = fmaxf(rm0, __shfl_xor_sync(0xffffffffu, rm0, off));
            rm1 = fmaxf(rm1, __shfl_xor_sync(0xffffffffu, rm1, off));
        }
        if (t == 0) {
            redM[wk * 64 + wq + g]     = rm0;
            redM[wk * 64 + wq + g + 8] = rm1;
        }
        __syncthreads();
        const float mx0 = fmaxf(redM[wq + g],     redM[64 + wq + g]);
        const float mx1 = fmaxf(redM[wq + g + 8], redM[64 + wq + g + 8]);
        const float mn0 = fmaxf(m0r, mx0), mn1 = fmaxf(m1r, mx1);
        const float al0 = __expf(m0r - mn0), al1 = __expf(m1r - mn1);

        float rs0 = 0.0f, rs1 = 0.0f;
#pragma unroll
        for (int nt = 0; nt < 4; nt++) {
            s[nt][0] = __expf(s[nt][0] - mn0);
            s[nt][1] = __expf(s[nt][1] - mn0);
            s[nt][2] = __expf(s[nt][2] - mn1);
            s[nt][3] = __expf(s[nt][3] - mn1);
            rs0 += s[nt][0] + s[nt][1];
            rs1 += s[nt][2] + s[nt][3];
            const int cb = wk * 32 + nt * 8 + 2 * t;
            *(float2*)&Ps[(wq + g)     * PS + cb] =
                make_float2(f2tff(s[nt][0]), f2tff(s[nt][1]));
            *(float2*)&Ps[(wq + g + 8) * PS + cb] =
                make_float2(f2tff(s[nt][2]), f2tff(s[nt][3]));
        }
#pragma unroll
        for (int off = 1; off <= 2; off <<= 1) {
            rs0 += __shfl_xor_sync(0xffffffffu, rs0, off);
            rs1 += __shfl_xor_sync(0xffffffffu, rs1, off);
        }
        if (t == 0) {
            redS[wk * 64 + wq + g]     = rs0;
            redS[wk * 64 + wq + g + 8] = rs1;
        }
        __syncthreads();
        l0 = l0 * al0 + redS[wq + g]     + redS[64 + wq + g];
        l1 = l1 * al1 + redS[wq + g + 8] + redS[64 + wq + g + 8];
        m0r = mn0; m1r = mn1;

#pragma unroll
        for (int nt = 0; nt < 8; nt++) {
            O[nt][0] *= al0; O[nt][1] *= al0;
            O[nt][2] *= al1; O[nt][3] *= al1;
        }

        // ---- O += P V (warp: 16q x 64d) ----
#pragma unroll
        for (int ks = 0; ks < 64; ks += 8) {
            unsigned af[4] = { Pu[(wq + g)     * PS + ks + t],
                               Pu[(wq + g + 8) * PS + ks + t],
                               Pu[(wq + g)     * PS + ks + t + 4],
                               Pu[(wq + g + 8) * PS + ks + t + 4] };
#pragma unroll
            for (int nt = 0; nt < 8; nt++) {
                const int d0 = wk * 64 + nt * 8;
                unsigned bf[2] = { Vu[(ks + t)     * VS + d0 + g],
                                   Vu[(ks + t + 4) * VS + d0 + g] };
                mma8(O[nt], af, bf);
            }
        }
    }

    const float inv0 = 1.0f / l0, inv1 = 1.0f / l1;
#pragma unroll
    for (int nt = 0; nt < 8; nt++) {
        const int col = h * HD + wk * 64 + nt * 8 + 2 * t;
        const size_t r0 = (size_t)(b * SEQL + qt * 64 + wq + g)     * DIM + col;
        const size_t r1 = (size_t)(b * SEQL + qt * 64 + wq + g + 8) * DIM + col;
        *(float2*)&outp[r0] = make_float2(O[nt][0] * inv0, O[nt][1] * inv0);
        *(float2*)&outp[r1] = make_float2(O[nt][2] * inv1, O[nt][3] * inv1);
    }
}

// ---------------------------------------------------------------------------
extern "C" void kernel_launch(void* const* d_in, const int* in_sizes, int n_in,
                              void* d_out, int out_size)
{
    const float* x  = (const float*)d_in[0];
    const float* pk = (const float*)d_in[1];
    const float* pv = (const float*)d_in[2];
    const float* wq = (const float*)d_in[4];
    const float* wk = (const float*)d_in[5];
    const float* wv = (const float*)d_in[6];
    const float* wo = (const float*)d_in[7];

    float* out  = (float*)d_out;
    float* kall = out  + (size_t)BATCH * SEQL * DIM;
    float* vall = kall + (size_t)BATCH * TTOT * DIM;

    float *qbuf, *abuf;
    cudaGetSymbolAddress((void**)&qbuf, g_q);
    cudaGetSymbolAddress((void**)&abuf, g_attn);

    for (int b = 0; b < BATCH; b++) {
        cudaMemcpyAsync(kall + (size_t)b * TTOT * DIM, pk + (size_t)b * HISTL * DIM,
                        (size_t)HISTL * DIM * sizeof(float), cudaMemcpyDeviceToDevice, 0);
        cudaMemcpyAsync(vall + (size_t)b * TTOT * DIM, pv + (size_t)b * HISTL * DIM,
                        (size_t)HISTL * DIM * sizeof(float), cudaMemcpyDeviceToDevice, 0);
    }

    dim3 ggrid(DIM / 128, MROWS / 128);
    gemm_tf32<<<ggrid, 256>>>(x, wq, qbuf, 0);
    gemm_tf32<<<ggrid, 256>>>(x, wk, kall, 1);
    gemm_tf32<<<ggrid, 256>>>(x, wv, vall, 1);

    const size_t smem = (size_t)(64 * QS * 2 + 64 * VS + 64 * PS + 256) * sizeof(float);
    cudaFuncSetAttribute(attn_tf32, cudaFuncAttributeMaxDynamicSharedMemorySize, (int)smem);
    attn_tf32<<<dim3(SEQL / 64, NHEAD, BATCH), 256, smem>>>(qbuf, kall, vall, abuf);

    gemm_tf32<<<ggrid, 256>>>(abuf, wo, out, 0);
}

// round 3
// speedup vs baseline: 3.8161x; 1.5297x over previous
#include <cuda_runtime.h>
#include <cstdint>

#define BATCH 2
#define SEQL  2048
#define HISTL 2048
#define TTOT  4096
#define NHEAD 16
#define HD    128
#define DIM   2048
#define MROWS 4096

__device__ float g_q[(size_t)MROWS * DIM];
__device__ float g_attn[(size_t)MROWS * DIM];
__device__ float g_xr[(size_t)MROWS * DIM];
__device__ float g_wr[(size_t)4 * DIM * DIM];

__device__ __forceinline__ unsigned f2tf(float x) {
    unsigned u; asm("cvt.rna.tf32.f32 %0, %1;" : "=r"(u) : "f"(x)); return u;
}
__device__ __forceinline__ float f2tff(float x) { return __uint_as_float(f2tf(x)); }

__device__ __forceinline__ void mma8(float* c, const unsigned* a, const unsigned* b) {
    asm volatile("mma.sync.aligned.m16n8k8.row.col.f32.tf32.tf32.f32 "
                 "{%0,%1,%2,%3}, {%4,%5,%6,%7}, {%8,%9}, {%0,%1,%2,%3};"
                 : "+f"(c[0]), "+f"(c[1]), "+f"(c[2]), "+f"(c[3])
                 : "r"(a[0]), "r"(a[1]), "r"(a[2]), "r"(a[3]),
                   "r"(b[0]), "r"(b[1]));
}

__device__ __forceinline__ void cp16(float* s, const float* g) {
    unsigned sa = (unsigned)__cvta_generic_to_shared(s);
    asm volatile("cp.async.cg.shared.global [%0], [%1], 16;" :: "r"(sa), "l"(g));
}
__device__ __forceinline__ void cp_commit() { asm volatile("cp.async.commit_group;"); }
__device__ __forceinline__ void cp_wait1()  { asm volatile("cp.async.wait_group 1;"); }

// ---------------------------------------------------------------------------
// tf32 rounding pass (elementwise, float4)
// ---------------------------------------------------------------------------
__global__ void round_tf32_kernel(const float* __restrict__ in, float* __restrict__ out, int n4)
{
    int i = blockIdx.x * blockDim.x + threadIdx.x;
    if (i < n4) {
        float4 v = ((const float4*)in)[i];
        ((float4*)out)[i] = make_float4(f2tff(v.x), f2tff(v.y), f2tff(v.z), f2tff(v.w));
    }
}

// ---------------------------------------------------------------------------
// TF32 GEMM NT, cp.async 3-stage: C[m,n] = sum_k A[m,k]*B[n,k]
// Inputs pre-rounded to tf32. mode 0: row-major out; mode 1: KV-concat remap.
// ---------------------------------------------------------------------------
#define RS 20
#define GST 3
#define GTILE (128 * RS)

__global__ __launch_bounds__(256) void gemm_tf32p(
    const float* __restrict__ A, const float* __restrict__ Bw,
    float* __restrict__ C, int mode)
{
    extern __shared__ __align__(16) float gsm[];
    float* As = gsm;                 // [GST][128*RS]
    float* Bs = gsm + GST * GTILE;   // [GST][128*RS]

    const int tid = threadIdx.x, lane = tid & 31, warp = tid >> 5;
    const int g = lane >> 2, t = lane & 3;
    const int wm = (warp >> 2) * 64;
    const int wn = (warp & 3) * 32;
    const int bm = blockIdx.y * 128, bn = blockIdx.x * 128;
    const int lr = tid >> 1, lc = (tid & 1) * 8;

    const float* Ap = A  + (size_t)(bm + lr) * DIM + lc;
    const float* Bp = Bw + (size_t)(bn + lr) * DIM + lc;

    float acc[4][4][4];
#pragma unroll
    for (int i = 0; i < 4; i++)
#pragma unroll
        for (int j = 0; j < 4; j++)
#pragma unroll
            for (int c = 0; c < 4; c++) acc[i][j][c] = 0.0f;

#define G_ISSUE(kb, s) do { \
    cp16(&As[(s)*GTILE + lr*RS + lc],     Ap + (kb)); \
    cp16(&As[(s)*GTILE + lr*RS + lc + 4], Ap + (kb) + 4); \
    cp16(&Bs[(s)*GTILE + lr*RS + lc],     Bp + (kb)); \
    cp16(&Bs[(s)*GTILE + lr*RS + lc + 4], Bp + (kb) + 4); \
} while (0)

    G_ISSUE(0, 0);  cp_commit();
    G_ISSUE(16, 1); cp_commit();

    const int nk = DIM / 16;
    for (int it = 0; it < nk; it++) {
        cp_wait1();
        __syncthreads();
        if (it + 2 < nk) { G_ISSUE((it + 2) * 16, (it + 2) % GST); }
        cp_commit();

        const unsigned* Asu = (const unsigned*)(As + (it % GST) * GTILE);
        const unsigned* Bsu = (const unsigned*)(Bs + (it % GST) * GTILE);
#pragma unroll
        for (int ks = 0; ks < 16; ks += 8) {
            unsigned af[4][4];
#pragma unroll
            for (int mt = 0; mt < 4; mt++) {
                const int m0 = wm + mt * 16;
                af[mt][0] = Asu[(m0 + g)     * RS + ks + t];
                af[mt][1] = Asu[(m0 + g + 8) * RS + ks + t];
                af[mt][2] = Asu[(m0 + g)     * RS + ks + t + 4];
                af[mt][3] = Asu[(m0 + g + 8) * RS + ks + t + 4];
            }
#pragma unroll
            for (int nt = 0; nt < 4; nt++) {
                const int n0 = wn + nt * 8;
                unsigned bf[2] = { Bsu[(n0 + g) * RS + ks + t],
                                   Bsu[(n0 + g) * RS + ks + t + 4] };
#pragma unroll
                for (int mt = 0; mt < 4; mt++) mma8(acc[mt][nt], af[mt], bf);
            }
        }
    }

#pragma unroll
    for (int mt = 0; mt < 4; mt++) {
        const int m0 = bm + wm + mt * 16 + g;
        const int m1 = m0 + 8;
        size_t ro0, ro1;
        if (mode == 0) {
            ro0 = (size_t)m0 * DIM; ro1 = (size_t)m1 * DIM;
        } else {
            ro0 = ((size_t)(m0 >> 11) * TTOT + HISTL + (m0 & 2047)) * DIM;
            ro1 = ((size_t)(m1 >> 11) * TTOT + HISTL + (m1 & 2047)) * DIM;
        }
#pragma unroll
        for (int nt = 0; nt < 4; nt++) {
            const int col = bn + wn + nt * 8 + 2 * t;
            *(float2*)&C[ro0 + col] = make_float2(acc[mt][nt][0], acc[mt][nt][1]);
            *(float2*)&C[ro1 + col] = make_float2(acc[mt][nt][2], acc[mt][nt][3]);
        }
    }
}

// ---------------------------------------------------------------------------
// TF32 flash attention v3: BQ=128 q rows/CTA, 8 warps, warp owns 16 full rows.
// Q register-resident; softmax stats via quad shuffles (no block syncs).
// ---------------------------------------------------------------------------
#define BQA 128
#define QSK 132   // K row stride (mod 32 == 4)
#define VSV 136   // V row stride (mod 32 == 8)
#define PSP 68    // P row stride (mod 32 == 4)

__global__ __launch_bounds__(256) void attn_tf32_v3(
    const float* __restrict__ q, const float* __restrict__ kall,
    const float* __restrict__ vall, float* __restrict__ outp)
{
    extern __shared__ __align__(16) float sm[];
    float* Ks = sm;               // [64][QSK]
    float* Vs = Ks + 64 * QSK;    // [64][VSV]
    float* Ps = Vs + 64 * VSV;    // [128][PSP] (warp-private row ranges)

    const int tid = threadIdx.x, lane = tid & 31, warp = tid >> 5;
    const int g = lane >> 2, t = lane & 3;
    const int qt = blockIdx.x, h = blockIdx.y, b = blockIdx.z;
    const int wq = warp * 16;

    // Q -> registers (tf32-rounded), 16 k-chunks of 8
    unsigned qa[16][4];
    {
        const size_t qbase = (size_t)(b * SEQL + qt * BQA + wq) * DIM + h * HD;
#pragma unroll
        for (int ks = 0; ks < 16; ks++) {
            qa[ks][0] = f2tf(q[qbase + (size_t)g       * DIM + ks * 8 + t]);
            qa[ks][1] = f2tf(q[qbase + (size_t)(g + 8) * DIM + ks * 8 + t]);
            qa[ks][2] = f2tf(q[qbase + (size_t)g       * DIM + ks * 8 + t + 4]);
            qa[ks][3] = f2tf(q[qbase + (size_t)(g + 8) * DIM + ks * 8 + t + 4]);
        }
    }

    float O[16][4];
#pragma unroll
    for (int i = 0; i < 16; i++)
#pragma unroll
        for (int c = 0; c < 4; c++) O[i][c] = 0.0f;
    float m0 = -1e30f, m1 = -1e30f, l0 = 0.0f, l1 = 0.0f;

    const int ntiles = HISTL / 64 + 2 * qt + 2;
    const float scale = 0.08838834764831845f;

    const unsigned* Ku = (const unsigned*)Ks;
    const unsigned* Vu = (const unsigned*)Vs;
    const unsigned* Pu = (const unsigned*)Ps;

    for (int kt = 0; kt < ntiles; kt++) {
        __syncthreads();
        for (int li = tid; li < 64 * 32; li += 256) {
            const int r = li >> 5, c = (li & 31) * 4;
            const size_t gg = (size_t)(b * TTOT + kt * 64 + r) * DIM + h * HD + c;
            float4 k4 = *(const float4*)&kall[gg];
            *(float4*)&Ks[r * QSK + c] =
                make_float4(f2tff(k4.x), f2tff(k4.y), f2tff(k4.z), f2tff(k4.w));
            float4 v4 = *(const float4*)&vall[gg];
            *(float4*)&Vs[r * VSV + c] =
                make_float4(f2tff(v4.x), f2tff(v4.y), f2tff(v4.z), f2tff(v4.w));
        }
        __syncthreads();

        // ---- S = Q K^T : warp computes 16q x 64kv ----
        float s[8][4];
#pragma unroll
        for (int nt = 0; nt < 8; nt++)
#pragma unroll
            for (int c = 0; c < 4; c++) s[nt][c] = 0.0f;

#pragma unroll
        for (int ks = 0; ks < 16; ks++) {
#pragma unroll
            for (int nt = 0; nt < 8; nt++) {
                unsigned bf[2] = { Ku[(nt * 8 + g) * QSK + ks * 8 + t],
                                   Ku[(nt * 8 + g) * QSK + ks * 8 + t + 4] };
                mma8(s[nt], qa[ks], bf);
            }
        }

        // scale + causal mask (only last two tiles can mask)
        const bool needmask = (kt >= ntiles - 2);
        const int diagoff = HISTL + qt * BQA - kt * 64;
#pragma unroll
        for (int nt = 0; nt < 8; nt++) {
#pragma unroll
            for (int c = 0; c < 4; c++) {
                float v = s[nt][c] * scale;
                if (needmask) {
                    const int row = wq + g + ((c >= 2) ? 8 : 0);
                    const int col = nt * 8 + 2 * t + (c & 1);
                    if (col > row + diagoff) v = -1e30f;
                }
                s[nt][c] = v;
            }
        }

        // row stats via quad shuffle (lanes g*4+t share rows g / g+8)
        float rm0 = -1e30f, rm1 = -1e30f;
#pragma unroll
        for (int nt = 0; nt < 8; nt++) {
            rm0 = fmaxf(rm0, fmaxf(s[nt][0], s[nt][1]));
            rm1 = fmaxf(rm1, fmaxf(s[nt][2], s[nt][3]));
        }
#pragma unroll
        for (int off = 1; off <= 2; off <<= 1) {
            rm0 = fmaxf(rm0, __shfl_xor_sync(0xffffffffu, rm0, off));
            rm1 = fmaxf(rm1, __shfl_xor_sync(0xffffffffu, rm1, off));
        }
        const float mn0 = fmaxf(m0, rm0), mn1 = fmaxf(m1, rm1);
        const float al0 = __expf(m0 - mn0), al1 = __expf(m1 - mn1);

        float rs0 = 0.0f, rs1 = 0.0f;
#pragma unroll
        for (int nt = 0; nt < 8; nt++) {
            float p0 = __expf(s[nt][0] - mn0);
            float p1 = __expf(s[nt][1] - mn0);
            float p2 = __expf(s[nt][2] - mn1);
            float p3 = __expf(s[nt][3] - mn1);
            rs0 += p0 + p1; rs1 += p2 + p3;
            const int cb = nt * 8 + 2 * t;
            *(float2*)&Ps[(wq + g)     * PSP + cb] = make_float2(f2tff(p0), f2tff(p1));
            *(float2*)&Ps[(wq + g + 8) * PSP + cb] = make_float2(f2tff(p2), f2tff(p3));
        }
#pragma unroll
        for (int off = 1; off <= 2; off <<= 1) {
            rs0 += __shfl_xor_sync(0xffffffffu, rs0, off);
            rs1 += __shfl_xor_sync(0xffffffffu, rs1, off);
        }
        l0 = l0 * al0 + rs0;
        l1 = l1 * al1 + rs1;
        m0 = mn0; m1 = mn1;

#pragma unroll
        for (int nt = 0; nt < 16; nt++) {
            O[nt][0] *= al0; O[nt][1] *= al0;
            O[nt][2] *= al1; O[nt][3] *= al1;
        }
        __syncwarp();

        // ---- O += P V : warp computes 16q x 128d ----
#pragma unroll
        for (int ks = 0; ks < 8; ks++) {
            unsigned af[4] = { Pu[(wq + g)     * PSP + ks * 8 + t],
                               Pu[(wq + g + 8) * PSP + ks * 8 + t],
                               Pu[(wq + g)     * PSP + ks * 8 + t + 4],
                               Pu[(wq + g + 8) * PSP + ks * 8 + t + 4] };
#pragma unroll
            for (int nt = 0; nt < 16; nt++) {
                unsigned bf[2] = { Vu[(ks * 8 + t)     * VSV + nt * 8 + g],
                                   Vu[(ks * 8 + t + 4) * VSV + nt * 8 + g] };
                mma8(O[nt], af, bf);
            }
        }
        __syncwarp();
    }

    const float inv0 = 1.0f / l0, inv1 = 1.0f / l1;
#pragma unroll
    for (int nt = 0; nt < 16; nt++) {
        const int col = h * HD + nt * 8 + 2 * t;
        const size_t r0 = (size_t)(b * SEQL + qt * BQA + wq + g)     * DIM + col;
        const size_t r1 = (size_t)(b * SEQL + qt * BQA + wq + g + 8) * DIM + col;
        // pre-round: this buffer feeds the final GEMM as A
        *(float2*)&outp[r0] = make_float2(f2tff(O[nt][0] * inv0), f2tff(O[nt][1] * inv0));
        *(float2*)&outp[r1] = make_float2(f2tff(O[nt][2] * inv1), f2tff(O[nt][3] * inv1));
    }
}

// ---------------------------------------------------------------------------
extern "C" void kernel_launch(void* const* d_in, const int* in_sizes, int n_in,
                              void* d_out, int out_size)
{
    const float* x  = (const float*)d_in[0];
    const float* pk = (const float*)d_in[1];
    const float* pv = (const float*)d_in[2];
    const float* wq = (const float*)d_in[4];
    const float* wk = (const float*)d_in[5];
    const float* wv = (const float*)d_in[6];
    const float* wo = (const float*)d_in[7];

    float* out  = (float*)d_out;
    float* kall = out  + (size_t)BATCH * SEQL * DIM;
    float* vall = kall + (size_t)BATCH * TTOT * DIM;

    float *qbuf, *abuf, *xr, *wr;
    cudaGetSymbolAddress((void**)&qbuf, g_q);
    cudaGetSymbolAddress((void**)&abuf, g_attn);
    cudaGetSymbolAddress((void**)&xr,   g_xr);
    cudaGetSymbolAddress((void**)&wr,   g_wr);

    // History concat
    for (int b = 0; b < BATCH; b++) {
        cudaMemcpyAsync(kall + (size_t)b * TTOT * DIM, pk + (size_t)b * HISTL * DIM,
                        (size_t)HISTL * DIM * sizeof(float), cudaMemcpyDeviceToDevice, 0);
        cudaMemcpyAsync(vall + (size_t)b * TTOT * DIM, pv + (size_t)b * HISTL * DIM,
                        (size_t)HISTL * DIM * sizeof(float), cudaMemcpyDeviceToDevice, 0);
    }

    // Pre-round GEMM inputs to tf32
    {
        const int nx4 = MROWS * DIM / 4, nw4 = DIM * DIM / 4;
        round_tf32_kernel<<<(nx4 + 255) / 256, 256>>>(x, xr, nx4);
        round_tf32_kernel<<<(nw4 + 255) / 256, 256>>>(wq, wr + 0 * (size_t)DIM * DIM, nw4);
        round_tf32_kernel<<<(nw4 + 255) / 256, 256>>>(wk, wr + 1 * (size_t)DIM * DIM, nw4);
        round_tf32_kernel<<<(nw4 + 255) / 256, 256>>>(wv, wr + 2 * (size_t)DIM * DIM, nw4);
        round_tf32_kernel<<<(nw4 + 255) / 256, 256>>>(wo, wr + 3 * (size_t)DIM * DIM, nw4);
    }

    const int gsm = (int)(2u * GST * GTILE * sizeof(float));  // 61440
    cudaFuncSetAttribute(gemm_tf32p, cudaFuncAttributeMaxDynamicSharedMemorySize, gsm);

    dim3 ggrid(DIM / 128, MROWS / 128);
    gemm_tf32p<<<ggrid, 256, gsm>>>(xr, wr + 0 * (size_t)DIM * DIM, qbuf, 0);
    gemm_tf32p<<<ggrid, 256, gsm>>>(xr, wr + 1 * (size_t)DIM * DIM, kall, 1);
    gemm_tf32p<<<ggrid, 256, gsm>>>(xr, wr + 2 * (size_t)DIM * DIM, vall, 1);

    const int asm_ = (int)((64 * QSK + 64 * VSV + 128 * PSP) * sizeof(float)); // 103424
    cudaFuncSetAttribute(attn_tf32_v3, cudaFuncAttributeMaxDynamicSharedMemorySize, asm_);
    attn_tf32_v3<<<dim3(SEQL / BQA, NHEAD, BATCH), 256, asm_>>>(qbuf, kall, vall, abuf);

    gemm_tf32p<<<ggrid, 256, gsm>>>(abuf, wr + 3 * (size_t)DIM * DIM, out, 0);
}

// round 6
// speedup vs baseline: 3.8237x; 1.0020x over previous
#include <cuda_runtime.h>
#include <cstdint>

#define BATCH 2
#define SEQL  2048
#define HISTL 2048
#define TTOT  4096
#define NHEAD 16
#define HD    128
#define DIM   2048
#define MROWS 4096

__device__ float g_q[(size_t)MROWS * DIM];
__device__ float g_attn[(size_t)MROWS * DIM];
__device__ float g_xr[(size_t)MROWS * DIM];
__device__ float g_wr[(size_t)4 * DIM * DIM];
__device__ float g_kr[(size_t)BATCH * TTOT * DIM];
__device__ float g_vr[(size_t)BATCH * TTOT * DIM];

__device__ __forceinline__ unsigned f2tf(float x) {
    unsigned u; asm("cvt.rna.tf32.f32 %0, %1;" : "=r"(u) : "f"(x)); return u;
}
__device__ __forceinline__ float f2tff(float x) { return __uint_as_float(f2tf(x)); }

__device__ __forceinline__ void mma8(float* c, const unsigned* a, const unsigned* b) {
    asm volatile("mma.sync.aligned.m16n8k8.row.col.f32.tf32.tf32.f32 "
                 "{%0,%1,%2,%3}, {%4,%5,%6,%7}, {%8,%9}, {%0,%1,%2,%3};"
                 : "+f"(c[0]), "+f"(c[1]), "+f"(c[2]), "+f"(c[3])
                 : "r"(a[0]), "r"(a[1]), "r"(a[2]), "r"(a[3]),
                   "r"(b[0]), "r"(b[1]));
}

__device__ __forceinline__ void cp16(float* s, const float* g) {
    unsigned sa = (unsigned)__cvta_generic_to_shared(s);
    asm volatile("cp.async.cg.shared.global [%0], [%1], 16;" :: "r"(sa), "l"(g));
}
__device__ __forceinline__ void cp_commit() { asm volatile("cp.async.commit_group;"); }
__device__ __forceinline__ void cp_wait1()  { asm volatile("cp.async.wait_group 1;"); }

// ---------------------------------------------------------------------------
// tf32 rounding pass
// ---------------------------------------------------------------------------
__global__ void round_tf32_kernel(const float* __restrict__ in, float* __restrict__ out, int n4)
{
    int i = blockIdx.x * blockDim.x + threadIdx.x;
    if (i < n4) {
        float4 v = ((const float4*)in)[i];
        ((float4*)out)[i] = make_float4(f2tff(v.x), f2tff(v.y), f2tff(v.z), f2tff(v.w));
    }
}

// ---------------------------------------------------------------------------
// TF32 GEMM NT, 256x128 CTA tile, 8 warps (4m x 2n), warp tile 64x64.
// C[m,n] = sum_k A[m,k]*B[n,k]. Inputs pre-rounded tf32.
// mode 0: row-major out; mode 1: KV-concat remap.
// ---------------------------------------------------------------------------
#define RS 20
#define A_STF (256 * RS)          // 5120 floats
#define B_STF (128 * RS)          // 2560 floats
#define STAGE_F (A_STF + B_STF)   // 7680 floats
#define GST 3

__global__ __launch_bounds__(256) void gemm_tf32w(
    const float* __restrict__ A, const float* __restrict__ Bw,
    float* __restrict__ C, int mode)
{
    extern __shared__ __align__(16) float gsm[];

    const int tid = threadIdx.x, lane = tid & 31, warp = tid >> 5;
    const int g = lane >> 2, t = lane & 3;
    const int wm = (warp >> 1) * 64;   // 0,64,128,192
    const int wn = (warp & 1) * 64;    // 0,64
    const int bm = blockIdx.y * 256, bn = blockIdx.x * 128;

    const float* Ap = A  + (size_t)(bm + tid) * DIM;
    const float* Bp = Bw + (size_t)(bn + (tid >> 1)) * DIM + (tid & 1) * 8;
    const int brow = (tid >> 1), bcol = (tid & 1) * 8;

    float acc[4][8][4];
#pragma unroll
    for (int i = 0; i < 4; i++)
#pragma unroll
        for (int j = 0; j < 8; j++)
#pragma unroll
            for (int c = 0; c < 4; c++) acc[i][j][c] = 0.0f;

#define G2_ISSUE(kb, s) do { \
    float* As_ = gsm + (s) * STAGE_F; \
    float* Bs_ = As_ + A_STF; \
    cp16(&As_[tid * RS + 0],  Ap + (kb)); \
    cp16(&As_[tid * RS + 4],  Ap + (kb) + 4); \
    cp16(&As_[tid * RS + 8],  Ap + (kb) + 8); \
    cp16(&As_[tid * RS + 12], Ap + (kb) + 12); \
    cp16(&Bs_[brow * RS + bcol],     Bp + (kb)); \
    cp16(&Bs_[brow * RS + bcol + 4], Bp + (kb) + 4); \
} while (0)

    G2_ISSUE(0, 0);  cp_commit();
    G2_ISSUE(16, 1); cp_commit();

    const int nk = DIM / 16;  // 128
    for (int it = 0; it < nk; it++) {
        cp_wait1();
        __syncthreads();
        if (it + 2 < nk) { G2_ISSUE((it + 2) * 16, (it + 2) % GST); }
        cp_commit();

        const unsigned* Asu = (const unsigned*)(gsm + (it % GST) * STAGE_F);
        const unsigned* Bsu = Asu + A_STF;
#pragma unroll
        for (int ks = 0; ks < 16; ks += 8) {
            unsigned af[4][4];
#pragma unroll
            for (int mt = 0; mt < 4; mt++) {
                const int m0 = wm + mt * 16;
                af[mt][0] = Asu[(m0 + g)     * RS + ks + t];
                af[mt][1] = Asu[(m0 + g + 8) * RS + ks + t];
                af[mt][2] = Asu[(m0 + g)     * RS + ks + t + 4];
                af[mt][3] = Asu[(m0 + g + 8) * RS + ks + t + 4];
            }
#pragma unroll
            for (int nt = 0; nt < 8; nt++) {
                const int n0 = wn + nt * 8;
                unsigned bf[2] = { Bsu[(n0 + g) * RS + ks + t],
                                   Bsu[(n0 + g) * RS + ks + t + 4] };
#pragma unroll
                for (int mt = 0; mt < 4; mt++) mma8(acc[mt][nt], af[mt], bf);
            }
        }
    }

#pragma unroll
    for (int mt = 0; mt < 4; mt++) {
        const int m0 = bm + wm + mt * 16 + g;
        const int m1 = m0 + 8;
        size_t ro0, ro1;
        if (mode == 0) {
            ro0 = (size_t)m0 * DIM; ro1 = (size_t)m1 * DIM;
        } else {
            ro0 = ((size_t)(m0 >> 11) * TTOT + HISTL + (m0 & 2047)) * DIM;
            ro1 = ((size_t)(m1 >> 11) * TTOT + HISTL + (m1 & 2047)) * DIM;
        }
#pragma unroll
        for (int nt = 0; nt < 8; nt++) {
            const int col = bn + wn + nt * 8 + 2 * t;
            *(float2*)&C[ro0 + col] = make_float2(acc[mt][nt][0], acc[mt][nt][1]);
            *(float2*)&C[ro1 + col] = make_float2(acc[mt][nt][2], acc[mt][nt][3]);
        }
    }
}

// ---------------------------------------------------------------------------
// TF32 flash attention v4: BQ=128, warp owns 16 rows, Q in registers,
// K/V pre-rounded in gmem, double-buffered cp.async tiles (64 kv/tile).
// ---------------------------------------------------------------------------
#define BQA 128
#define KSTR 132
#define VSTR 136
#define PSTR 68

__global__ __launch_bounds__(256) void attn_tf32_v4(
    const float* __restrict__ q, const float* __restrict__ kr,
    const float* __restrict__ vr, float* __restrict__ outp)
{
    extern __shared__ __align__(16) float sm[];
    float* K0 = sm;                    // [64][KSTR]
    float* K1 = K0 + 64 * KSTR;
    float* V0 = K1 + 64 * KSTR;        // [64][VSTR]
    float* V1 = V0 + 64 * VSTR;
    float* Ps = V1 + 64 * VSTR;        // [128][PSTR]

    const int tid = threadIdx.x, lane = tid & 31, warp = tid >> 5;
    const int g = lane >> 2, t = lane & 3;
    const int qt = blockIdx.x, h = blockIdx.y, b = blockIdx.z;
    const int wq = warp * 16;

    const size_t kvbase0 = (size_t)b * TTOT * DIM + h * HD;

#define KV_ISSUE(kt, st) do { \
    float* Kd = (st) ? K1 : K0; \
    float* Vd = (st) ? V1 : V0; \
    const size_t gb = kvbase0 + (size_t)((kt) * 64) * DIM; \
    _Pragma("unroll") \
    for (int i = 0; i < 8; i++) { \
        const int chunk = tid + 256 * i; \
        const int r = chunk >> 5, c = (chunk & 31) * 4; \
        cp16(&Kd[r * KSTR + c], kr + gb + (size_t)r * DIM + c); \
        cp16(&Vd[r * VSTR + c], vr + gb + (size_t)r * DIM + c); \
    } \
} while (0)

    // Q -> registers (tf32-rounded)
    unsigned qa[16][4];
    {
        const size_t qbase = (size_t)(b * SEQL + qt * BQA + wq) * DIM + h * HD;
#pragma unroll
        for (int ks = 0; ks < 16; ks++) {
            qa[ks][0] = f2tf(q[qbase + (size_t)g       * DIM + ks * 8 + t]);
            qa[ks][1] = f2tf(q[qbase + (size_t)(g + 8) * DIM + ks * 8 + t]);
            qa[ks][2] = f2tf(q[qbase + (size_t)g       * DIM + ks * 8 + t + 4]);
            qa[ks][3] = f2tf(q[qbase + (size_t)(g + 8) * DIM + ks * 8 + t + 4]);
        }
    }

    float O[16][4];
#pragma unroll
    for (int i = 0; i < 16; i++)
#pragma unroll
        for (int c = 0; c < 4; c++) O[i][c] = 0.0f;
    float m0 = -1e30f, m1 = -1e30f, l0 = 0.0f, l1 = 0.0f;

    const int ntiles = HISTL / 64 + 2 * qt + 2;
    const float scale = 0.08838834764831845f;

    KV_ISSUE(0, 0); cp_commit();

    const unsigned* Pu = (const unsigned*)Ps;

    for (int kt = 0; kt < ntiles; kt++) {
        __syncthreads();   // all warps done computing tile kt-1 -> stage reusable
        if (kt + 1 < ntiles) { KV_ISSUE(kt + 1, (kt + 1) & 1); }
        cp_commit();
        cp_wait1();        // tile kt resident
        __syncthreads();

        const unsigned* Ku = (const unsigned*)((kt & 1) ? K1 : K0);
        const unsigned* Vu = (const unsigned*)((kt & 1) ? V1 : V0);

        // ---- S = Q K^T : warp computes 16q x 64kv ----
        float s[8][4];
#pragma unroll
        for (int nt = 0; nt < 8; nt++)
#pragma unroll
            for (int c = 0; c < 4; c++) s[nt][c] = 0.0f;

#pragma unroll
        for (int ks = 0; ks < 16; ks++) {
#pragma unroll
            for (int nt = 0; nt < 8; nt++) {
                unsigned bf[2] = { Ku[(nt * 8 + g) * KSTR + ks * 8 + t],
                                   Ku[(nt * 8 + g) * KSTR + ks * 8 + t + 4] };
                mma8(s[nt], qa[ks], bf);
            }
        }

        const bool needmask = (kt >= ntiles - 2);
        const int diagoff = HISTL + qt * BQA - kt * 64;
#pragma unroll
        for (int nt = 0; nt < 8; nt++) {
#pragma unroll
            for (int c = 0; c < 4; c++) {
                float v = s[nt][c] * scale;
                if (needmask) {
                    const int rrow = wq + g + ((c >= 2) ? 8 : 0);
                    const int col = nt * 8 + 2 * t + (c & 1);
                    if (col > rrow + diagoff) v = -1e30f;
                }
                s[nt][c] = v;
            }
        }

        float rm0 = -1e30f, rm1 = -1e30f;
#pragma unroll
        for (int nt = 0; nt < 8; nt++) {
            rm0 = fmaxf(rm0, fmaxf(s[nt][0], s[nt][1]));
            rm1 = fmaxf(rm1, fmaxf(s[nt][2], s[nt][3]));
        }
#pragma unroll
        for (int off = 1; off <= 2; off <<= 1) {
            rm0 = fmaxf(rm0, __shfl_xor_sync(0xffffffffu, rm0, off));
            rm1 = fmaxf(rm1, __shfl_xor_sync(0xffffffffu, rm1, off));
        }
        const float mn0 = fmaxf(m0, rm0), mn1 = fmaxf(m1, rm1);
        const float al0 = __expf(m0 - mn0), al1 = __expf(m1 - mn1);

        float rs0 = 0.0f, rs1 = 0.0f;
#pragma unroll
        for (int nt = 0; nt < 8; nt++) {
            float p0 = __expf(s[nt][0] - mn0);
            float p1 = __expf(s[nt][1] - mn0);
            float p2 = __expf(s[nt][2] - mn1);
            float p3 = __expf(s[nt][3] - mn1);
            rs0 += p0 + p1; rs1 += p2 + p3;
            const int cb = nt * 8 + 2 * t;
            *(float2*)&Ps[(wq + g)     * PSTR + cb] = make_float2(f2tff(p0), f2tff(p1));
            *(float2*)&Ps[(wq + g + 8) * PSTR + cb] = make_float2(f2tff(p2), f2tff(p3));
        }
#pragma unroll
        for (int off = 1; off <= 2; off <<= 1) {
            rs0 += __shfl_xor_sync(0xffffffffu, rs0, off);
            rs1 += __shfl_xor_sync(0xffffffffu, rs1, off);
        }
        l0 = l0 * al0 + rs0;
        l1 = l1 * al1 + rs1;
        m0 = mn0; m1 = mn1;

#pragma unroll
        for (int nt = 0; nt < 16; nt++) {
            O[nt][0] *= al0; O[nt][1] *= al0;
            O[nt][2] *= al1; O[nt][3] *= al1;
        }
        __syncwarp();

        // ---- O += P V : warp computes 16q x 128d ----
#pragma unroll
        for (int ks = 0; ks < 8; ks++) {
            unsigned af[4] = { Pu[(wq + g)     * PSTR + ks * 8 + t],
                               Pu[(wq + g + 8) * PSTR + ks * 8 + t],
                               Pu[(wq + g)     * PSTR + ks * 8 + t + 4],
                               Pu[(wq + g + 8) * PSTR + ks * 8 + t + 4] };
#pragma unroll
            for (int nt = 0; nt < 16; nt++) {
                unsigned bf[2] = { Vu[(ks * 8 + t)     * VSTR + nt * 8 + g],
                                   Vu[(ks * 8 + t + 4) * VSTR + nt * 8 + g] };
                mma8(O[nt], af, bf);
            }
        }
        __syncwarp();
    }

    const float inv0 = 1.0f / l0, inv1 = 1.0f / l1;
#pragma unroll
    for (int nt = 0; nt < 16; nt++) {
        const int col = h * HD + nt * 8 + 2 * t;
        const size_t r0 = (size_t)(b * SEQL + qt * BQA + wq + g)     * DIM + col;
        const size_t r1 = (size_t)(b * SEQL + qt * BQA + wq + g + 8) * DIM + col;
        *(float2*)&outp[r0] = make_float2(f2tff(O[nt][0] * inv0), f2tff(O[nt][1] * inv0));
        *(float2*)&outp[r1] = make_float2(f2tff(O[nt][2] * inv1), f2tff(O[nt][3] * inv1));
    }
}

// ---------------------------------------------------------------------------
extern "C" void kernel_launch(void* const* d_in, const int* in_sizes, int n_in,
                              void* d_out, int out_size)
{
    const float* x  = (const float*)d_in[0];
    const float* pk = (const float*)d_in[1];
    const float* pv = (const float*)d_in[2];
    const float* wq = (const float*)d_in[4];
    const float* wk = (const float*)d_in[5];
    const float* wv = (const float*)d_in[6];
    const float* wo = (const float*)d_in[7];

    float* out  = (float*)d_out;
    float* kall = out  + (size_t)BATCH * SEQL * DIM;
    float* vall = kall + (size_t)BATCH * TTOT * DIM;

    float *qbuf, *abuf, *xr, *wr, *krb, *vrb;
    cudaGetSymbolAddress((void**)&qbuf, g_q);
    cudaGetSymbolAddress((void**)&abuf, g_attn);
    cudaGetSymbolAddress((void**)&xr,   g_xr);
    cudaGetSymbolAddress((void**)&wr,   g_wr);
    cudaGetSymbolAddress((void**)&krb,  g_kr);
    cudaGetSymbolAddress((void**)&vrb,  g_vr);

    for (int b = 0; b < BATCH; b++) {
        cudaMemcpyAsync(kall + (size_t)b * TTOT * DIM, pk + (size_t)b * HISTL * DIM,
                        (size_t)HISTL * DIM * sizeof(float), cudaMemcpyDeviceToDevice, 0);
        cudaMemcpyAsync(vall + (size_t)b * TTOT * DIM, pv + (size_t)b * HISTL * DIM,
                        (size_t)HISTL * DIM * sizeof(float), cudaMemcpyDeviceToDevice, 0);
    }

    {
        const int nx4 = MROWS * DIM / 4, nw4 = DIM * DIM / 4;
        round_tf32_kernel<<<(nx4 + 255) / 256, 256>>>(x, xr, nx4);
        round_tf32_kernel<<<(nw4 + 255) / 256, 256>>>(wq, wr + 0 * (size_t)DIM * DIM, nw4);
        round_tf32_kernel<<<(nw4 + 255) / 256, 256>>>(wk, wr + 1 * (size_t)DIM * DIM, nw4);
        round_tf32_kernel<<<(nw4 + 255) / 256, 256>>>(wv, wr + 2 * (size_t)DIM * DIM, nw4);
        round_tf32_kernel<<<(nw4 + 255) / 256, 256>>>(wo, wr + 3 * (size_t)DIM * DIM, nw4);
    }

    const int gsm = (int)(GST * STAGE_F * sizeof(float));  // 92160
    cudaFuncSetAttribute(gemm_tf32w, cudaFuncAttributeMaxDynamicSharedMemorySize, gsm);

    dim3 ggrid(DIM / 128, MROWS / 256);
    gemm_tf32w<<<ggrid, 256, gsm>>>(xr, wr + 0 * (size_t)DIM * DIM, qbuf, 0);
    gemm_tf32w<<<ggrid, 256, gsm>>>(xr, wr + 1 * (size_t)DIM * DIM, kall, 1);
    gemm_tf32w<<<ggrid, 256, gsm>>>(xr, wr + 2 * (size_t)DIM * DIM, vall, 1);

    // rounded K/V copies for attention consumption
    {
        const int nkv4 = BATCH * TTOT * DIM / 4;
        round_tf32_kernel<<<(nkv4 + 255) / 256, 256>>>(kall, krb, nkv4);
        round_tf32_kernel<<<(nkv4 + 255) / 256, 256>>>(vall, vrb, nkv4);
    }

    const int asm_ = (int)((2 * 64 * KSTR + 2 * 64 * VSTR + 128 * PSTR) * sizeof(float)); // 172032
    cudaFuncSetAttribute(attn_tf32_v4, cudaFuncAttributeMaxDynamicSharedMemorySize, asm_);
    attn_tf32_v4<<<dim3(SEQL / BQA, NHEAD, BATCH), 256, asm_>>>(qbuf, krb, vrb, abuf);

    gemm_tf32w<<<ggrid, 256, gsm>>>(abuf, wr + 3 * (size_t)DIM * DIM, out, 0);
}

// round 7
// speedup vs baseline: 4.0963x; 1.0713x over previous
#include <cuda_runtime.h>
#include <cstdint>

#define BATCH 2
#define SEQL  2048
#define HISTL 2048
#define TTOT  4096
#define NHEAD 16
#define HD    128
#define DIM   2048
#define MROWS 4096

__device__ float g_q[(size_t)MROWS * DIM];
__device__ float g_attn[(size_t)MROWS * DIM];
__device__ float g_xr[(size_t)MROWS * DIM];
__device__ float g_wr[(size_t)4 * DIM * DIM];
__device__ float g_kr[(size_t)BATCH * TTOT * DIM];
__device__ float g_vr[(size_t)BATCH * TTOT * DIM];

__device__ __forceinline__ unsigned f2tf(float x) {
    unsigned u; asm("cvt.rna.tf32.f32 %0, %1;" : "=r"(u) : "f"(x)); return u;
}
__device__ __forceinline__ float f2tff(float x) { return __uint_as_float(f2tf(x)); }

__device__ __forceinline__ void mma8(float* c, const unsigned* a, const unsigned* b) {
    asm volatile("mma.sync.aligned.m16n8k8.row.col.f32.tf32.tf32.f32 "
                 "{%0,%1,%2,%3}, {%4,%5,%6,%7}, {%8,%9}, {%0,%1,%2,%3};"
                 : "+f"(c[0]), "+f"(c[1]), "+f"(c[2]), "+f"(c[3])
                 : "r"(a[0]), "r"(a[1]), "r"(a[2]), "r"(a[3]),
                   "r"(b[0]), "r"(b[1]));
}

__device__ __forceinline__ void cp16(float* s, const float* g) {
    unsigned sa = (unsigned)__cvta_generic_to_shared(s);
    asm volatile("cp.async.cg.shared.global [%0], [%1], 16;" :: "r"(sa), "l"(g));
}
__device__ __forceinline__ void cp_commit() { asm volatile("cp.async.commit_group;"); }
__device__ __forceinline__ void cp_wait1()  { asm volatile("cp.async.wait_group 1;"); }

// ---------------------------------------------------------------------------
// tf32 rounding pass, 4 float4 per thread (MLP=4)
// ---------------------------------------------------------------------------
__global__ void round_tf32_kernel(const float* __restrict__ in, float* __restrict__ out, int n4)
{
    const int base = blockIdx.x * blockDim.x * 4 + threadIdx.x;
    const int str = blockDim.x;
    float4 v[4];
    int idx[4];
#pragma unroll
    for (int i = 0; i < 4; i++) {
        idx[i] = base + i * str;
        if (idx[i] < n4) v[i] = ((const float4*)in)[idx[i]];
    }
#pragma unroll
    for (int i = 0; i < 4; i++)
        if (idx[i] < n4)
            ((float4*)out)[idx[i]] =
                make_float4(f2tff(v[i].x), f2tff(v[i].y), f2tff(v[i].z), f2tff(v[i].w));
}

// ---------------------------------------------------------------------------
// History concat + round: prev -> dst_exact (kall/vall[:, :HISTL]) and
// rounded -> dst_round. Handles K and V in one launch.
// ---------------------------------------------------------------------------
__global__ void concat_round_kernel(
    const float* __restrict__ pk, const float* __restrict__ pv,
    float* __restrict__ kall, float* __restrict__ vall,
    float* __restrict__ krb,  float* __restrict__ vrb)
{
    const int n4 = BATCH * HISTL * DIM / 4;          // per tensor
    const int i = blockIdx.x * blockDim.x + threadIdx.x;
    const int e = (i >= n4) ? (i - n4) : i;
    if (i >= 2 * n4) return;
    const int bb = e / (HISTL * DIM / 4);
    const int rem = e - bb * (HISTL * DIM / 4);
    const int dOff = bb * (TTOT * DIM / 4) + rem;
    const float* src = (i < n4) ? pk : pv;
    float* de = (i < n4) ? kall : vall;
    float* dr = (i < n4) ? krb : vrb;
    float4 v = ((const float4*)src)[e];
    ((float4*)de)[dOff] = v;
    ((float4*)dr)[dOff] = make_float4(f2tff(v.x), f2tff(v.y), f2tff(v.z), f2tff(v.w));
}

// ---------------------------------------------------------------------------
// TF32 GEMM NT, 128x128 tile, cp.async 3-stage, 2 CTAs/SM.
// mode via CR: CR==null -> row-major exact out only;
// CR!=null -> KV remap, exact to C + rounded to CR.
// ---------------------------------------------------------------------------
#define RS 20
#define GST 3
#define GTILE (128 * RS)

__global__ __launch_bounds__(256, 2) void gemm_tf32p(
    const float* __restrict__ A, const float* __restrict__ Bw,
    float* __restrict__ C, float* __restrict__ CR)
{
    extern __shared__ __align__(16) float gsm[];
    float* As = gsm;
    float* Bs = gsm + GST * GTILE;

    const int tid = threadIdx.x, lane = tid & 31, warp = tid >> 5;
    const int g = lane >> 2, t = lane & 3;
    const int wm = (warp >> 2) * 64;
    const int wn = (warp & 3) * 32;
    const int bm = blockIdx.y * 128, bn = blockIdx.x * 128;
    const int lr = tid >> 1, lc = (tid & 1) * 8;

    const float* Ap = A  + (size_t)(bm + lr) * DIM + lc;
    const float* Bp = Bw + (size_t)(bn + lr) * DIM + lc;

    float acc[4][4][4];
#pragma unroll
    for (int i = 0; i < 4; i++)
#pragma unroll
        for (int j = 0; j < 4; j++)
#pragma unroll
            for (int c = 0; c < 4; c++) acc[i][j][c] = 0.0f;

#define G_ISSUE(kb, s) do { \
    cp16(&As[(s)*GTILE + lr*RS + lc],     Ap + (kb)); \
    cp16(&As[(s)*GTILE + lr*RS + lc + 4], Ap + (kb) + 4); \
    cp16(&Bs[(s)*GTILE + lr*RS + lc],     Bp + (kb)); \
    cp16(&Bs[(s)*GTILE + lr*RS + lc + 4], Bp + (kb) + 4); \
} while (0)

    G_ISSUE(0, 0);  cp_commit();
    G_ISSUE(16, 1); cp_commit();

    const int nk = DIM / 16;
    for (int it = 0; it < nk; it++) {
        cp_wait1();
        __syncthreads();
        if (it + 2 < nk) { G_ISSUE((it + 2) * 16, (it + 2) % GST); }
        cp_commit();

        const unsigned* Asu = (const unsigned*)(As + (it % GST) * GTILE);
        const unsigned* Bsu = (const unsigned*)(Bs + (it % GST) * GTILE);
#pragma unroll
        for (int ks = 0; ks < 16; ks += 8) {
            unsigned af[4][4];
#pragma unroll
            for (int mt = 0; mt < 4; mt++) {
                const int m0 = wm + mt * 16;
                af[mt][0] = Asu[(m0 + g)     * RS + ks + t];
                af[mt][1] = Asu[(m0 + g + 8) * RS + ks + t];
                af[mt][2] = Asu[(m0 + g)     * RS + ks + t + 4];
                af[mt][3] = Asu[(m0 + g + 8) * RS + ks + t + 4];
            }
#pragma unroll
            for (int nt = 0; nt < 4; nt++) {
                const int n0 = wn + nt * 8;
                unsigned bf[2] = { Bsu[(n0 + g) * RS + ks + t],
                                   Bsu[(n0 + g) * RS + ks + t + 4] };
#pragma unroll
                for (int mt = 0; mt < 4; mt++) mma8(acc[mt][nt], af[mt], bf);
            }
        }
    }

#pragma unroll
    for (int mt = 0; mt < 4; mt++) {
        const int m0 = bm + wm + mt * 16 + g;
        const int m1 = m0 + 8;
        size_t ro0, ro1;
        if (CR == nullptr) {
            ro0 = (size_t)m0 * DIM; ro1 = (size_t)m1 * DIM;
        } else {
            ro0 = ((size_t)(m0 >> 11) * TTOT + HISTL + (m0 & 2047)) * DIM;
            ro1 = ((size_t)(m1 >> 11) * TTOT + HISTL + (m1 & 2047)) * DIM;
        }
#pragma unroll
        for (int nt = 0; nt < 4; nt++) {
            const int col = bn + wn + nt * 8 + 2 * t;
            *(float2*)&C[ro0 + col] = make_float2(acc[mt][nt][0], acc[mt][nt][1]);
            *(float2*)&C[ro1 + col] = make_float2(acc[mt][nt][2], acc[mt][nt][3]);
            if (CR != nullptr) {
                *(float2*)&CR[ro0 + col] =
                    make_float2(f2tff(acc[mt][nt][0]), f2tff(acc[mt][nt][1]));
                *(float2*)&CR[ro1 + col] =
                    make_float2(f2tff(acc[mt][nt][2]), f2tff(acc[mt][nt][3]));
            }
        }
    }
}

// ---------------------------------------------------------------------------
// TF32 flash attention v4 (R5, unchanged): BQ=128, Q in regs, K/V pre-rounded,
// double-buffered cp.async tiles.
// ---------------------------------------------------------------------------
#define BQA 128
#define KSTR 132
#define VSTR 136
#define PSTR 68

__global__ __launch_bounds__(256) void attn_tf32_v4(
    const float* __restrict__ q, const float* __restrict__ kr,
    const float* __restrict__ vr, float* __restrict__ outp)
{
    extern __shared__ __align__(16) float sm[];
    float* K0 = sm;
    float* K1 = K0 + 64 * KSTR;
    float* V0 = K1 + 64 * KSTR;
    float* V1 = V0 + 64 * VSTR;
    float* Ps = V1 + 64 * VSTR;

    const int tid = threadIdx.x, lane = tid & 31, warp = tid >> 5;
    const int g = lane >> 2, t = lane & 3;
    const int qt = blockIdx.x, h = blockIdx.y, b = blockIdx.z;
    const int wq = warp * 16;

    const size_t kvbase0 = (size_t)b * TTOT * DIM + h * HD;

#define KV_ISSUE(kt, st) do { \
    float* Kd = (st) ? K1 : K0; \
    float* Vd = (st) ? V1 : V0; \
    const size_t gb = kvbase0 + (size_t)((kt) * 64) * DIM; \
    _Pragma("unroll") \
    for (int i = 0; i < 8; i++) { \
        const int chunk = tid + 256 * i; \
        const int r = chunk >> 5, c = (chunk & 31) * 4; \
        cp16(&Kd[r * KSTR + c], kr + gb + (size_t)r * DIM + c); \
        cp16(&Vd[r * VSTR + c], vr + gb + (size_t)r * DIM + c); \
    } \
} while (0)

    unsigned qa[16][4];
    {
        const size_t qbase = (size_t)(b * SEQL + qt * BQA + wq) * DIM + h * HD;
#pragma unroll
        for (int ks = 0; ks < 16; ks++) {
            qa[ks][0] = f2tf(q[qbase + (size_t)g       * DIM + ks * 8 + t]);
            qa[ks][1] = f2tf(q[qbase + (size_t)(g + 8) * DIM + ks * 8 + t]);
            qa[ks][2] = f2tf(q[qbase + (size_t)g       * DIM + ks * 8 + t + 4]);
            qa[ks][3] = f2tf(q[qbase + (size_t)(g + 8) * DIM + ks * 8 + t + 4]);
        }
    }

    float O[16][4];
#pragma unroll
    for (int i = 0; i < 16; i++)
#pragma unroll
        for (int c = 0; c < 4; c++) O[i][c] = 0.0f;
    float m0 = -1e30f, m1 = -1e30f, l0 = 0.0f, l1 = 0.0f;

    const int ntiles = HISTL / 64 + 2 * qt + 2;
    const float scale = 0.08838834764831845f;

    KV_ISSUE(0, 0); cp_commit();

    const unsigned* Pu = (const unsigned*)Ps;

    for (int kt = 0; kt < ntiles; kt++) {
        __syncthreads();
        if (kt + 1 < ntiles) { KV_ISSUE(kt + 1, (kt + 1) & 1); }
        cp_commit();
        cp_wait1();
        __syncthreads();

        const unsigned* Ku = (const unsigned*)((kt & 1) ? K1 : K0);
        const unsigned* Vu = (const unsigned*)((kt & 1) ? V1 : V0);

        float s[8][4];
#pragma unroll
        for (int nt = 0; nt < 8; nt++)
#pragma unroll
            for (int c = 0; c < 4; c++) s[nt][c] = 0.0f;

#pragma unroll
        for (int ks = 0; ks < 16; ks++) {
#pragma unroll
            for (int nt = 0; nt < 8; nt++) {
                unsigned bf[2] = { Ku[(nt * 8 + g) * KSTR + ks * 8 + t],
                                   Ku[(nt * 8 + g) * KSTR + ks * 8 + t + 4] };
                mma8(s[nt], qa[ks], bf);
            }
        }

        const bool needmask = (kt >= ntiles - 2);
        const int diagoff = HISTL + qt * BQA - kt * 64;
#pragma unroll
        for (int nt = 0; nt < 8; nt++) {
#pragma unroll
            for (int c = 0; c < 4; c++) {
                float v = s[nt][c] * scale;
                if (needmask) {
                    const int rrow = wq + g + ((c >= 2) ? 8 : 0);
                    const int col = nt * 8 + 2 * t + (c & 1);
                    if (col > rrow + diagoff) v = -1e30f;
                }
                s[nt][c] = v;
            }
        }

        float rm0 = -1e30f, rm1 = -1e30f;
#pragma unroll
        for (int nt = 0; nt < 8; nt++) {
            rm0 = fmaxf(rm0, fmaxf(s[nt][0], s[nt][1]));
            rm1 = fmaxf(rm1, fmaxf(s[nt][2], s[nt][3]));
        }
#pragma unroll
        for (int off = 1; off <= 2; off <<= 1) {
            rm0 = fmaxf(rm0, __shfl_xor_sync(0xffffffffu, rm0, off));
            rm1 = fmaxf(rm1, __shfl_xor_sync(0xffffffffu, rm1, off));
        }
        const float mn0 = fmaxf(m0, rm0), mn1 = fmaxf(m1, rm1);
        const float al0 = __expf(m0 - mn0), al1 = __expf(m1 - mn1);

        float rs0 = 0.0f, rs1 = 0.0f;
#pragma unroll
        for (int nt = 0; nt < 8; nt++) {
            float p0 = __expf(s[nt][0] - mn0);
            float p1 = __expf(s[nt][1] - mn0);
            float p2 = __expf(s[nt][2] - mn1);
            float p3 = __expf(s[nt][3] - mn1);
            rs0 += p0 + p1; rs1 += p2 + p3;
            const int cb = nt * 8 + 2 * t;
            *(float2*)&Ps[(wq + g)     * PSTR + cb] = make_float2(f2tff(p0), f2tff(p1));
            *(float2*)&Ps[(wq + g + 8) * PSTR + cb] = make_float2(f2tff(p2), f2tff(p3));
        }
#pragma unroll
        for (int off = 1; off <= 2; off <<= 1) {
            rs0 += __shfl_xor_sync(0xffffffffu, rs0, off);
            rs1 += __shfl_xor_sync(0xffffffffu, rs1, off);
        }
        l0 = l0 * al0 + rs0;
        l1 = l1 * al1 + rs1;
        m0 = mn0; m1 = mn1;

#pragma unroll
        for (int nt = 0; nt < 16; nt++) {
            O[nt][0] *= al0; O[nt][1] *= al0;
            O[nt][2] *= al1; O[nt][3] *= al1;
        }
        __syncwarp();

#pragma unroll
        for (int ks = 0; ks < 8; ks++) {
            unsigned af[4] = { Pu[(wq + g)     * PSTR + ks * 8 + t],
                               Pu[(wq + g + 8) * PSTR + ks * 8 + t],
                               Pu[(wq + g)     * PSTR + ks * 8 + t + 4],
                               Pu[(wq + g + 8) * PSTR + ks * 8 + t + 4] };
#pragma unroll
            for (int nt = 0; nt < 16; nt++) {
                unsigned bf[2] = { Vu[(ks * 8 + t)     * VSTR + nt * 8 + g],
                                   Vu[(ks * 8 + t + 4) * VSTR + nt * 8 + g] };
                mma8(O[nt], af, bf);
            }
        }
        __syncwarp();
    }

    const float inv0 = 1.0f / l0, inv1 = 1.0f / l1;
#pragma unroll
    for (int nt = 0; nt < 16; nt++) {
        const int col = h * HD + nt * 8 + 2 * t;
        const size_t r0 = (size_t)(b * SEQL + qt * BQA + wq + g)     * DIM + col;
        const size_t r1 = (size_t)(b * SEQL + qt * BQA + wq + g + 8) * DIM + col;
        *(float2*)&outp[r0] = make_float2(f2tff(O[nt][0] * inv0), f2tff(O[nt][1] * inv0));
        *(float2*)&outp[r1] = make_float2(f2tff(O[nt][2] * inv1), f2tff(O[nt][3] * inv1));
    }
}

// ---------------------------------------------------------------------------
extern "C" void kernel_launch(void* const* d_in, const int* in_sizes, int n_in,
                              void* d_out, int out_size)
{
    const float* x  = (const float*)d_in[0];
    const float* pk = (const float*)d_in[1];
    const float* pv = (const float*)d_in[2];
    const float* wq = (const float*)d_in[4];
    const float* wk = (const float*)d_in[5];
    const float* wv = (const float*)d_in[6];
    const float* wo = (const float*)d_in[7];

    float* out  = (float*)d_out;
    float* kall = out  + (size_t)BATCH * SEQL * DIM;
    float* vall = kall + (size_t)BATCH * TTOT * DIM;

    float *qbuf, *abuf, *xr, *wr, *krb, *vrb;
    cudaGetSymbolAddress((void**)&qbuf, g_q);
    cudaGetSymbolAddress((void**)&abuf, g_attn);
    cudaGetSymbolAddress((void**)&xr,   g_xr);
    cudaGetSymbolAddress((void**)&wr,   g_wr);
    cudaGetSymbolAddress((void**)&krb,  g_kr);
    cudaGetSymbolAddress((void**)&vrb,  g_vr);

    // History concat + rounded copy (replaces 4 memcpys + 2 round passes)
    {
        const int tot = 2 * BATCH * HISTL * DIM / 4;
        concat_round_kernel<<<(tot + 255) / 256, 256>>>(pk, pv, kall, vall, krb, vrb);
    }

    // Pre-round GEMM inputs to tf32
    {
        const int nx4 = MROWS * DIM / 4, nw4 = DIM * DIM / 4;
        round_tf32_kernel<<<(nx4 + 1023) / 1024, 256>>>(x, xr, nx4);
        round_tf32_kernel<<<(nw4 + 1023) / 1024, 256>>>(wq, wr + 0 * (size_t)DIM * DIM, nw4);
        round_tf32_kernel<<<(nw4 + 1023) / 1024, 256>>>(wk, wr + 1 * (size_t)DIM * DIM, nw4);
        round_tf32_kernel<<<(nw4 + 1023) / 1024, 256>>>(wv, wr + 2 * (size_t)DIM * DIM, nw4);
        round_tf32_kernel<<<(nw4 + 1023) / 1024, 256>>>(wo, wr + 3 * (size_t)DIM * DIM, nw4);
    }

    const int gsm = (int)(2u * GST * GTILE * sizeof(float));  // 61440
    cudaFuncSetAttribute(gemm_tf32p, cudaFuncAttributeMaxDynamicSharedMemorySize, gsm);

    dim3 ggrid(DIM / 128, MROWS / 128);
    gemm_tf32p<<<ggrid, 256, gsm>>>(xr, wr + 0 * (size_t)DIM * DIM, qbuf, nullptr);
    gemm_tf32p<<<ggrid, 256, gsm>>>(xr, wr + 1 * (size_t)DIM * DIM, kall, krb);
    gemm_tf32p<<<ggrid, 256, gsm>>>(xr, wr + 2 * (size_t)DIM * DIM, vall, vrb);

    const int asm_ = (int)((2 * 64 * KSTR + 2 * 64 * VSTR + 128 * PSTR) * sizeof(float));
    cudaFuncSetAttribute(attn_tf32_v4, cudaFuncAttributeMaxDynamicSharedMemorySize, asm_);
    attn_tf32_v4<<<dim3(SEQL / BQA, NHEAD, BATCH), 256, asm_>>>(qbuf, krb, vrb, abuf);

    gemm_tf32p<<<ggrid, 256, gsm>>>(abuf, wr + 3 * (size_t)DIM * DIM, out, nullptr);
}

// round 8
// speedup vs baseline: 7.2975x; 1.7815x over previous
#include <cuda_runtime.h>
#include <cuda_fp16.h>
#include <cstdint>

#define BATCH 2
#define SEQL  2048
#define HISTL 2048
#define TTOT  4096
#define NHEAD 16
#define HD    128
#define DIM   2048
#define MROWS 4096

__device__ float  g_q[(size_t)MROWS * DIM];
__device__ __half g_ah[(size_t)MROWS * DIM];
__device__ __half g_xh[(size_t)MROWS * DIM];
__device__ __half g_wh[(size_t)4 * DIM * DIM];
__device__ __half g_kh[(size_t)BATCH * TTOT * DIM];
__device__ __half g_vt[(size_t)BATCH * NHEAD * HD * TTOT];

__device__ __forceinline__ unsigned h2u(__half2 h) { return *(unsigned*)&h; }

__device__ __forceinline__ void mma16(float* c, const unsigned* a, const unsigned* b) {
    asm volatile("mma.sync.aligned.m16n8k16.row.col.f32.f16.f16.f32 "
                 "{%0,%1,%2,%3}, {%4,%5,%6,%7}, {%8,%9}, {%0,%1,%2,%3};"
                 : "+f"(c[0]), "+f"(c[1]), "+f"(c[2]), "+f"(c[3])
                 : "r"(a[0]), "r"(a[1]), "r"(a[2]), "r"(a[3]),
                   "r"(b[0]), "r"(b[1]));
}

__device__ __forceinline__ void cp16h(__half* s, const __half* g) {
    unsigned sa = (unsigned)__cvta_generic_to_shared(s);
    asm volatile("cp.async.cg.shared.global [%0], [%1], 16;" :: "r"(sa), "l"(g));
}
__device__ __forceinline__ void cp_commit() { asm volatile("cp.async.commit_group;"); }
__device__ __forceinline__ void cp_wait1()  { asm volatile("cp.async.wait_group 1;"); }

// ---------------------------------------------------------------------------
// f32 -> f16 conversion pass
// ---------------------------------------------------------------------------
__global__ void cvt_f16_kernel(const float* __restrict__ in, __half* __restrict__ out, int n4)
{
    int i = blockIdx.x * blockDim.x + threadIdx.x;
    if (i < n4) {
        float4 v = ((const float4*)in)[i];
        ((uint2*)out)[i] = make_uint2(h2u(__floats2half2_rn(v.x, v.y)),
                                      h2u(__floats2half2_rn(v.z, v.w)));
    }
}

// ---------------------------------------------------------------------------
// History concat: prev_k/prev_v -> kall/vall[:, :HISTL] (f32) + K half copy
// ---------------------------------------------------------------------------
__global__ void concat_half_kernel(
    const float* __restrict__ pk, const float* __restrict__ pv,
    float* __restrict__ kall, float* __restrict__ vall, __half* __restrict__ kh)
{
    const int n4 = BATCH * HISTL * DIM / 4;
    const int i = blockIdx.x * blockDim.x + threadIdx.x;
    if (i >= 2 * n4) return;
    const bool isK = (i < n4);
    const int e = isK ? i : (i - n4);
    const int bb = e / (HISTL * DIM / 4);
    const int rem = e - bb * (HISTL * DIM / 4);
    const int dOff = bb * (TTOT * DIM / 4) + rem;
    float4 v = ((const float4*)(isK ? pk : pv))[e];
    ((float4*)(isK ? kall : vall))[dOff] = v;
    if (isK)
        ((uint2*)kh)[dOff] = make_uint2(h2u(__floats2half2_rn(v.x, v.y)),
                                        h2u(__floats2half2_rn(v.z, v.w)));
}

// ---------------------------------------------------------------------------
// V transpose: vall f32 [b, kv, h, d] -> vt half [b, h, d, kv]
// block: 64 kv x 64 d for one (b,h)
// ---------------------------------------------------------------------------
__global__ void vtrans_kernel(const float* __restrict__ vall, __half* __restrict__ vt)
{
    __shared__ float smt[64][65];
    const int tid = threadIdx.x;
    const int kv0 = blockIdx.x * 64, d0 = blockIdx.y * 64;
    const int bh = blockIdx.z;                 // b*NHEAD + h
    const int b = bh >> 4, h = bh & 15;

    for (int idx = tid; idx < 64 * 16; idx += 256) {
        const int r = idx >> 4, c = (idx & 15) * 4;
        float4 v = *(const float4*)&vall[((size_t)b * TTOT + kv0 + r) * DIM + h * HD + d0 + c];
        smt[r][c] = v.x; smt[r][c + 1] = v.y; smt[r][c + 2] = v.z; smt[r][c + 3] = v.w;
    }
    __syncthreads();
    for (int idx = tid; idx < 64 * 8; idx += 256) {
        const int d = idx >> 3, ck = (idx & 7) * 8;
        unsigned u[4];
#pragma unroll
        for (int j = 0; j < 4; j++)
            u[j] = h2u(__floats2half2_rn(smt[ck + 2 * j][d], smt[ck + 2 * j + 1][d]));
        *(uint4*)&vt[((size_t)bh * HD + d0 + d) * TTOT + kv0 + ck] =
            make_uint4(u[0], u[1], u[2], u[3]);
    }
}

// ---------------------------------------------------------------------------
// FP16 GEMM NT: C[m,n] = sum_k A[m,k]*B[n,k] (f32 out), 128x128 tile,
// K-chunk 32, cp.async 3-stage, 2 CTAs/SM.
// remap: KV-concat row remap. CR: optional half dual-write (same layout as C).
// ---------------------------------------------------------------------------
#define RSH 40
#define GST 3
#define GTILEH (128 * RSH)

__global__ __launch_bounds__(256, 2) void gemm_f16(
    const __half* __restrict__ A, const __half* __restrict__ Bw,
    float* __restrict__ C, __half* __restrict__ CR, int remap)
{
    extern __shared__ __align__(16) __half hsm[];
    __half* As = hsm;
    __half* Bs = hsm + GST * GTILEH;

    const int tid = threadIdx.x, lane = tid & 31, warp = tid >> 5;
    const int g = lane >> 2, t = lane & 3;
    const int wm = (warp >> 2) * 64;
    const int wn = (warp & 3) * 32;
    const int bm = blockIdx.y * 128, bn = blockIdx.x * 128;

    const int row = tid >> 1, boff = (tid & 1) * 16;
    const __half* Ap = A  + (size_t)(bm + row) * DIM + boff;
    const __half* Bp = Bw + (size_t)(bn + row) * DIM + boff;

    float acc[4][4][4];
#pragma unroll
    for (int i = 0; i < 4; i++)
#pragma unroll
        for (int j = 0; j < 4; j++)
#pragma unroll
            for (int c = 0; c < 4; c++) acc[i][j][c] = 0.0f;

#define GH_ISSUE(kb, s) do { \
    cp16h(&As[(s)*GTILEH + row*RSH + boff],     Ap + (kb)); \
    cp16h(&As[(s)*GTILEH + row*RSH + boff + 8], Ap + (kb) + 8); \
    cp16h(&Bs[(s)*GTILEH + row*RSH + boff],     Bp + (kb)); \
    cp16h(&Bs[(s)*GTILEH + row*RSH + boff + 8], Bp + (kb) + 8); \
} while (0)

    GH_ISSUE(0, 0);  cp_commit();
    GH_ISSUE(32, 1); cp_commit();

    const int nk = DIM / 32;  // 64
    for (int it = 0; it < nk; it++) {
        cp_wait1();
        __syncthreads();
        if (it + 2 < nk) { GH_ISSUE((it + 2) * 32, (it + 2) % GST); }
        cp_commit();

        const unsigned* Asu = (const unsigned*)(As + (it % GST) * GTILEH);
        const unsigned* Bsu = (const unsigned*)(Bs + (it % GST) * GTILEH);
#pragma unroll
        for (int ks2 = 0; ks2 < 2; ks2++) {     // two k16 steps; half-idx ks2*16
            const int kx = ks2 * 8 + t;         // uint index base (RSH/2 = 20)
            unsigned af[4][4];
#pragma unroll
            for (int mt = 0; mt < 4; mt++) {
                const int m0 = wm + mt * 16;
                af[mt][0] = Asu[(m0 + g)     * 20 + kx];
                af[mt][1] = Asu[(m0 + g + 8) * 20 + kx];
                af[mt][2] = Asu[(m0 + g)     * 20 + kx + 4];
                af[mt][3] = Asu[(m0 + g + 8) * 20 + kx + 4];
            }
#pragma unroll
            for (int nt = 0; nt < 4; nt++) {
                const int n0 = wn + nt * 8;
                unsigned bf[2] = { Bsu[(n0 + g) * 20 + kx],
                                   Bsu[(n0 + g) * 20 + kx + 4] };
#pragma unroll
                for (int mt = 0; mt < 4; mt++) mma16(acc[mt][nt], af[mt], bf);
            }
        }
    }

#pragma unroll
    for (int mt = 0; mt < 4; mt++) {
        const int m0 = bm + wm + mt * 16 + g;
        const int m1 = m0 + 8;
        size_t ro0, ro1;
        if (!remap) {
            ro0 = (size_t)m0 * DIM; ro1 = (size_t)m1 * DIM;
        } else {
            ro0 = ((size_t)(m0 >> 11) * TTOT + HISTL + (m0 & 2047)) * DIM;
            ro1 = ((size_t)(m1 >> 11) * TTOT + HISTL + (m1 & 2047)) * DIM;
        }
#pragma unroll
        for (int nt = 0; nt < 4; nt++) {
            const int col = bn + wn + nt * 8 + 2 * t;
            *(float2*)&C[ro0 + col] = make_float2(acc[mt][nt][0], acc[mt][nt][1]);
            *(float2*)&C[ro1 + col] = make_float2(acc[mt][nt][2], acc[mt][nt][3]);
            if (CR != nullptr) {
                *(__half2*)&CR[ro0 + col] = __floats2half2_rn(acc[mt][nt][0], acc[mt][nt][1]);
                *(__half2*)&CR[ro1 + col] = __floats2half2_rn(acc[mt][nt][2], acc[mt][nt][3]);
            }
        }
    }
}

// ---------------------------------------------------------------------------
// FP16 flash attention: BQ=128, warp owns 16 rows, Q in half regs,
// K half [kv][d], V half transposed [d][kv], double-buffered cp.async.
// ---------------------------------------------------------------------------
#define BQA 128
#define KSH 136   // K row halves (128 data + 8)
#define VTH 72    // Vt row halves (64 data + 8)
#define PSH 72    // P row halves

__global__ __launch_bounds__(256) void attn_f16(
    const float* __restrict__ q, const __half* __restrict__ kh,
    const __half* __restrict__ vt, __half* __restrict__ outp)
{
    extern __shared__ __align__(16) __half smh[];
    __half* K0 = smh;                     // [64][KSH]
    __half* K1 = K0 + 64 * KSH;
    __half* V0 = K1 + 64 * KSH;           // [128][VTH] (d-major)
    __half* V1 = V0 + 128 * VTH;
    __half* Ps = V1 + 128 * VTH;          // [128][PSH]

    const int tid = threadIdx.x, lane = tid & 31, warp = tid >> 5;
    const int g = lane >> 2, t = lane & 3;
    const int qt = blockIdx.x, h = blockIdx.y, b = blockIdx.z;
    const int wq = warp * 16;

    const size_t kbase = (size_t)b * TTOT * DIM + h * HD;
    const size_t vbase = ((size_t)b * NHEAD + h) * HD * TTOT;

#define KV_ISSUE(kt, st) do { \
    __half* Kd = (st) ? K1 : K0; \
    __half* Vd = (st) ? V1 : V0; \
    const size_t kg = kbase + (size_t)((kt) * 64) * DIM; \
    const size_t vg = vbase + (kt) * 64; \
    _Pragma("unroll") \
    for (int i = 0; i < 4; i++) { \
        const int ck = tid + 256 * i; \
        const int kr = ck >> 4, ko = (ck & 15) * 8; \
        cp16h(&Kd[kr * KSH + ko], kh + kg + (size_t)kr * DIM + ko); \
        const int vr = ck >> 3, vo = (ck & 7) * 8; \
        cp16h(&Vd[vr * VTH + vo], vt + vg + (size_t)vr * TTOT + vo); \
    } \
} while (0)

    // Q -> half2 registers
    unsigned qa[8][4];
    {
        const size_t qbase = (size_t)(b * SEQL + qt * BQA + wq) * DIM + h * HD;
        const float* q0 = q + qbase + (size_t)g * DIM;
        const float* q1 = q + qbase + (size_t)(g + 8) * DIM;
#pragma unroll
        for (int kc = 0; kc < 8; kc++) {
            const int k0 = kc * 16 + 2 * t;
            qa[kc][0] = h2u(__floats2half2_rn(q0[k0],     q0[k0 + 1]));
            qa[kc][1] = h2u(__floats2half2_rn(q1[k0],     q1[k0 + 1]));
            qa[kc][2] = h2u(__floats2half2_rn(q0[k0 + 8], q0[k0 + 9]));
            qa[kc][3] = h2u(__floats2half2_rn(q1[k0 + 8], q1[k0 + 9]));
        }
    }

    float O[16][4];
#pragma unroll
    for (int i = 0; i < 16; i++)
#pragma unroll
        for (int c = 0; c < 4; c++) O[i][c] = 0.0f;
    float m0 = -1e30f, m1 = -1e30f, l0 = 0.0f, l1 = 0.0f;

    const int ntiles = HISTL / 64 + 2 * qt + 2;
    const float scale = 0.08838834764831845f;

    KV_ISSUE(0, 0); cp_commit();

    unsigned* Pu = (unsigned*)Ps;

    for (int kt = 0; kt < ntiles; kt++) {
        __syncthreads();
        if (kt + 1 < ntiles) { KV_ISSUE(kt + 1, (kt + 1) & 1); }
        cp_commit();
        cp_wait1();
        __syncthreads();

        const unsigned* Ku = (const unsigned*)((kt & 1) ? K1 : K0);
        const unsigned* Vu = (const unsigned*)((kt & 1) ? V1 : V0);

        // ---- S = Q K^T : 16q x 64kv per warp ----
        float s[8][4];
#pragma unroll
        for (int nt = 0; nt < 8; nt++)
#pragma unroll
            for (int c = 0; c < 4; c++) s[nt][c] = 0.0f;

#pragma unroll
        for (int kc = 0; kc < 8; kc++) {
#pragma unroll
            for (int nt = 0; nt < 8; nt++) {
                const int bi = (nt * 8 + g) * 68 + kc * 8 + t;   // KSH/2 = 68
                unsigned bf[2] = { Ku[bi], Ku[bi + 4] };
                mma16(s[nt], qa[kc], bf);
            }
        }

        const bool needmask = (kt >= ntiles - 2);
        const int diagoff = HISTL + qt * BQA - kt * 64;
#pragma unroll
        for (int nt = 0; nt < 8; nt++) {
#pragma unroll
            for (int c = 0; c < 4; c++) {
                float v = s[nt][c] * scale;
                if (needmask) {
                    const int rrow = wq + g + ((c >= 2) ? 8 : 0);
                    const int col = nt * 8 + 2 * t + (c & 1);
                    if (col > rrow + diagoff) v = -1e30f;
                }
                s[nt][c] = v;
            }
        }

        float rm0 = -1e30f, rm1 = -1e30f;
#pragma unroll
        for (int nt = 0; nt < 8; nt++) {
            rm0 = fmaxf(rm0, fmaxf(s[nt][0], s[nt][1]));
            rm1 = fmaxf(rm1, fmaxf(s[nt][2], s[nt][3]));
        }
#pragma unroll
        for (int off = 1; off <= 2; off <<= 1) {
            rm0 = fmaxf(rm0, __shfl_xor_sync(0xffffffffu, rm0, off));
            rm1 = fmaxf(rm1, __shfl_xor_sync(0xffffffffu, rm1, off));
        }
        const float mn0 = fmaxf(m0, rm0), mn1 = fmaxf(m1, rm1);
        const float al0 = __expf(m0 - mn0), al1 = __expf(m1 - mn1);

        float rs0 = 0.0f, rs1 = 0.0f;
#pragma unroll
        for (int nt = 0; nt < 8; nt++) {
            float p0 = __expf(s[nt][0] - mn0);
            float p1 = __expf(s[nt][1] - mn0);
            float p2 = __expf(s[nt][2] - mn1);
            float p3 = __expf(s[nt][3] - mn1);
            rs0 += p0 + p1; rs1 += p2 + p3;
            Pu[(wq + g)     * 36 + nt * 4 + t] = h2u(__floats2half2_rn(p0, p1));
            Pu[(wq + g + 8) * 36 + nt * 4 + t] = h2u(__floats2half2_rn(p2, p3));
        }
#pragma unroll
        for (int off = 1; off <= 2; off <<= 1) {
            rs0 += __shfl_xor_sync(0xffffffffu, rs0, off);
            rs1 += __shfl_xor_sync(0xffffffffu, rs1, off);
        }
        l0 = l0 * al0 + rs0;
        l1 = l1 * al1 + rs1;
        m0 = mn0; m1 = mn1;

#pragma unroll
        for (int nt = 0; nt < 16; nt++) {
            O[nt][0] *= al0; O[nt][1] *= al0;
            O[nt][2] *= al1; O[nt][3] *= al1;
        }
        __syncwarp();

        // ---- O += P V : 16q x 128d per warp ----
#pragma unroll
        for (int kc = 0; kc < 4; kc++) {
            unsigned af[4] = { Pu[(wq + g)     * 36 + kc * 8 + t],
                               Pu[(wq + g + 8) * 36 + kc * 8 + t],
                               Pu[(wq + g)     * 36 + kc * 8 + t + 4],
                               Pu[(wq + g + 8) * 36 + kc * 8 + t + 4] };
#pragma unroll
            for (int nt = 0; nt < 16; nt++) {
                const int bi = (nt * 8 + g) * 36 + kc * 8 + t;   // VTH/2 = 36
                unsigned bf[2] = { Vu[bi], Vu[bi + 4] };
                mma16(O[nt], af, bf);
            }
        }
        __syncwarp();
    }

    const float inv0 = 1.0f / l0, inv1 = 1.0f / l1;
#pragma unroll
    for (int nt = 0; nt < 16; nt++) {
        const int col = h * HD + nt * 8 + 2 * t;
        const size_t r0 = (size_t)(b * SEQL + qt * BQA + wq + g)     * DIM + col;
        const size_t r1 = (size_t)(b * SEQL + qt * BQA + wq + g + 8) * DIM + col;
        *(__half2*)&outp[r0] = __floats2half2_rn(O[nt][0] * inv0, O[nt][1] * inv0);
        *(__half2*)&outp[r1] = __floats2half2_rn(O[nt][2] * inv1, O[nt][3] * inv1);
    }
}

// ---------------------------------------------------------------------------
extern "C" void kernel_launch(void* const* d_in, const int* in_sizes, int n_in,
                              void* d_out, int out_size)
{
    const float* x  = (const float*)d_in[0];
    const float* pk = (const float*)d_in[1];
    const float* pv = (const float*)d_in[2];
    const float* wq = (const float*)d_in[4];
    const float* wk = (const float*)d_in[5];
    const float* wv = (const float*)d_in[6];
    const float* wo = (const float*)d_in[7];

    float* out  = (float*)d_out;
    float* kall = out  + (size_t)BATCH * SEQL * DIM;
    float* vall = kall + (size_t)BATCH * TTOT * DIM;

    float *qbuf; __half *ah, *xh, *wh, *kh, *vt;
    cudaGetSymbolAddress((void**)&qbuf, g_q);
    cudaGetSymbolAddress((void**)&ah,   g_ah);
    cudaGetSymbolAddress((void**)&xh,   g_xh);
    cudaGetSymbolAddress((void**)&wh,   g_wh);
    cudaGetSymbolAddress((void**)&kh,   g_kh);
    cudaGetSymbolAddress((void**)&vt,   g_vt);

    // History concat (f32 outputs) + K half copy
    {
        const int tot = 2 * BATCH * HISTL * DIM / 4;
        concat_half_kernel<<<(tot + 255) / 256, 256>>>(pk, pv, kall, vall, kh);
    }

    // Convert GEMM inputs to f16
    {
        const int nx4 = MROWS * DIM / 4, nw4 = DIM * DIM / 4;
        cvt_f16_kernel<<<(nx4 + 255) / 256, 256>>>(x, xh, nx4);
        cvt_f16_kernel<<<(nw4 + 255) / 256, 256>>>(wq, wh + 0 * (size_t)DIM * DIM, nw4);
        cvt_f16_kernel<<<(nw4 + 255) / 256, 256>>>(wk, wh + 1 * (size_t)DIM * DIM, nw4);
        cvt_f16_kernel<<<(nw4 + 255) / 256, 256>>>(wv, wh + 2 * (size_t)DIM * DIM, nw4);
        cvt_f16_kernel<<<(nw4 + 255) / 256, 256>>>(wo, wh + 3 * (size_t)DIM * DIM, nw4);
    }

    const int gsm = (int)(2u * GST * GTILEH * sizeof(__half));  // 61440
    cudaFuncSetAttribute(gemm_f16, cudaFuncAttributeMaxDynamicSharedMemorySize, gsm);

    dim3 ggrid(DIM / 128, MROWS / 128);
    gemm_f16<<<ggrid, 256, gsm>>>(xh, wh + 0 * (size_t)DIM * DIM, qbuf, nullptr, 0);
    gemm_f16<<<ggrid, 256, gsm>>>(xh, wh + 1 * (size_t)DIM * DIM, kall, kh, 1);
    gemm_f16<<<ggrid, 256, gsm>>>(xh, wh + 2 * (size_t)DIM * DIM, vall, nullptr, 1);

    // V transpose: vall f32 -> vt half [b,h,d,kv]
    vtrans_kernel<<<dim3(TTOT / 64, HD / 64, BATCH * NHEAD), 256>>>(vall, vt);

    const int asmh = (int)((2 * 64 * KSH + 2 * 128 * VTH + 128 * PSH) * sizeof(__half)); // 90112
    cudaFuncSetAttribute(attn_f16, cudaFuncAttributeMaxDynamicSharedMemorySize, asmh);
    attn_f16<<<dim3(SEQL / BQA, NHEAD, BATCH), 256, asmh>>>(qbuf, kh, vt, ah);

    gemm_f16<<<ggrid, 256, gsm>>>(ah, wh + 3 * (size_t)DIM * DIM, out, nullptr, 0);
}

// round 9
// speedup vs baseline: 7.4764x; 1.0245x over previous
#include <cuda_runtime.h>
#include <cuda_fp16.h>
#include <cstdint>

#define BATCH 2
#define SEQL  2048
#define HISTL 2048
#define TTOT  4096
#define NHEAD 16
#define HD    128
#define DIM   2048
#define MROWS 4096

__device__ float  g_q[(size_t)MROWS * DIM];
__device__ __half g_ah[(size_t)MROWS * DIM];
__device__ __half g_xh[(size_t)MROWS * DIM];
__device__ __half g_wh[(size_t)4 * DIM * DIM];
__device__ __half g_kh[(size_t)BATCH * TTOT * DIM];
__device__ __half g_vt[(size_t)BATCH * NHEAD * HD * TTOT];

__device__ __forceinline__ unsigned h2u(__half2 h) { return *(unsigned*)&h; }

__device__ __forceinline__ void mma16(float* c, const unsigned* a, const unsigned* b) {
    asm volatile("mma.sync.aligned.m16n8k16.row.col.f32.f16.f16.f32 "
                 "{%0,%1,%2,%3}, {%4,%5,%6,%7}, {%8,%9}, {%0,%1,%2,%3};"
                 : "+f"(c[0]), "+f"(c[1]), "+f"(c[2]), "+f"(c[3])
                 : "r"(a[0]), "r"(a[1]), "r"(a[2]), "r"(a[3]),
                   "r"(b[0]), "r"(b[1]));
}

__device__ __forceinline__ void ldm4(unsigned* r, uint32_t addr) {
    asm volatile("ldmatrix.sync.aligned.m8n8.x4.shared.b16 {%0,%1,%2,%3}, [%4];"
                 : "=r"(r[0]), "=r"(r[1]), "=r"(r[2]), "=r"(r[3]) : "r"(addr));
}

__device__ __forceinline__ void cp16h(__half* s, const __half* g) {
    unsigned sa = (unsigned)__cvta_generic_to_shared(s);
    asm volatile("cp.async.cg.shared.global [%0], [%1], 16;" :: "r"(sa), "l"(g));
}
__device__ __forceinline__ void cp_commit() { asm volatile("cp.async.commit_group;"); }
__device__ __forceinline__ void cp_wait1()  { asm volatile("cp.async.wait_group 1;"); }

// ---------------------------------------------------------------------------
// f32 -> f16 conversion (single tensor)
// ---------------------------------------------------------------------------
__global__ void cvt_f16_kernel(const float* __restrict__ in, __half* __restrict__ out, int n4)
{
    int i = blockIdx.x * blockDim.x + threadIdx.x;
    if (i < n4) {
        float4 v = ((const float4*)in)[i];
        ((uint2*)out)[i] = make_uint2(h2u(__floats2half2_rn(v.x, v.y)),
                                      h2u(__floats2half2_rn(v.z, v.w)));
    }
}

// 4 weights -> contiguous half buffer in one launch
__global__ void cvt_w4_kernel(const float* __restrict__ w0, const float* __restrict__ w1,
                              const float* __restrict__ w2, const float* __restrict__ w3,
                              __half* __restrict__ out)
{
    const int nw4 = DIM * DIM / 4;
    const int i = blockIdx.x * blockDim.x + threadIdx.x;
    if (i >= 4 * nw4) return;
    const int which = i / nw4, e = i - which * nw4;
    const float* src = (which == 0) ? w0 : (which == 1) ? w1 : (which == 2) ? w2 : w3;
    float4 v = ((const float4*)src)[e];
    ((uint2*)out)[i] = make_uint2(h2u(__floats2half2_rn(v.x, v.y)),
                                  h2u(__floats2half2_rn(v.z, v.w)));
}

// ---------------------------------------------------------------------------
// History concat: prev_k/prev_v -> kall/vall[:, :HISTL] (f32) + K half copy
// ---------------------------------------------------------------------------
__global__ void concat_half_kernel(
    const float* __restrict__ pk, const float* __restrict__ pv,
    float* __restrict__ kall, float* __restrict__ vall, __half* __restrict__ kh)
{
    const int n4 = BATCH * HISTL * DIM / 4;
    const int i = blockIdx.x * blockDim.x + threadIdx.x;
    if (i >= 2 * n4) return;
    const bool isK = (i < n4);
    const int e = isK ? i : (i - n4);
    const int bb = e / (HISTL * DIM / 4);
    const int rem = e - bb * (HISTL * DIM / 4);
    const int dOff = bb * (TTOT * DIM / 4) + rem;
    float4 v = ((const float4*)(isK ? pk : pv))[e];
    ((float4*)(isK ? kall : vall))[dOff] = v;
    if (isK)
        ((uint2*)kh)[dOff] = make_uint2(h2u(__floats2half2_rn(v.x, v.y)),
                                        h2u(__floats2half2_rn(v.z, v.w)));
}

// ---------------------------------------------------------------------------
// V transpose: vall f32 [b, kv, h, d] -> vt half [b, h, d, kv]
// ---------------------------------------------------------------------------
__global__ void vtrans_kernel(const float* __restrict__ vall, __half* __restrict__ vt)
{
    __shared__ float smt[64][65];
    const int tid = threadIdx.x;
    const int kv0 = blockIdx.x * 64, d0 = blockIdx.y * 64;
    const int bh = blockIdx.z;
    const int b = bh >> 4, h = bh & 15;

    for (int idx = tid; idx < 64 * 16; idx += 256) {
        const int r = idx >> 4, c = (idx & 15) * 4;
        float4 v = *(const float4*)&vall[((size_t)b * TTOT + kv0 + r) * DIM + h * HD + d0 + c];
        smt[r][c] = v.x; smt[r][c + 1] = v.y; smt[r][c + 2] = v.z; smt[r][c + 3] = v.w;
    }
    __syncthreads();
    for (int idx = tid; idx < 64 * 8; idx += 256) {
        const int d = idx >> 3, ck = (idx & 7) * 8;
        unsigned u[4];
#pragma unroll
        for (int j = 0; j < 4; j++)
            u[j] = h2u(__floats2half2_rn(smt[ck + 2 * j][d], smt[ck + 2 * j + 1][d]));
        *(uint4*)&vt[((size_t)bh * HD + d0 + d) * TTOT + kv0 + ck] =
            make_uint4(u[0], u[1], u[2], u[3]);
    }
}

// ---------------------------------------------------------------------------
// FP16 GEMM NT with ldmatrix fragment loads. 128x128 tile, K-chunk 32,
// cp.async 3-stage, 2 CTAs/SM.
// ---------------------------------------------------------------------------
#define RSH 40
#define GST 3
#define GTILEH (128 * RSH)

__global__ __launch_bounds__(256, 2) void gemm_f16(
    const __half* __restrict__ A, const __half* __restrict__ Bw,
    float* __restrict__ C, __half* __restrict__ CR, int remap)
{
    extern __shared__ __align__(16) __half hsm[];
    __half* As = hsm;
    __half* Bs = hsm + GST * GTILEH;

    const int tid = threadIdx.x, lane = tid & 31, warp = tid >> 5;
    const int g = lane >> 2, t = lane & 3;
    const int ln15 = lane & 15, hi8 = (lane >> 4) * 8;
    const int wm = (warp >> 2) * 64;
    const int wn = (warp & 3) * 32;
    const int bm = blockIdx.y * 128, bn = blockIdx.x * 128;

    const int row = tid >> 1, boff = (tid & 1) * 16;
    const __half* Ap = A  + (size_t)(bm + row) * DIM + boff;
    const __half* Bp = Bw + (size_t)(bn + row) * DIM + boff;

    const uint32_t As0 = (uint32_t)__cvta_generic_to_shared(As);
    const uint32_t Bs0 = (uint32_t)__cvta_generic_to_shared(Bs);

    float acc[4][4][4];
#pragma unroll
    for (int i = 0; i < 4; i++)
#pragma unroll
        for (int j = 0; j < 4; j++)
#pragma unroll
            for (int c = 0; c < 4; c++) acc[i][j][c] = 0.0f;

#define GH_ISSUE(kb, s) do { \
    cp16h(&As[(s)*GTILEH + row*RSH + boff],     Ap + (kb)); \
    cp16h(&As[(s)*GTILEH + row*RSH + boff + 8], Ap + (kb) + 8); \
    cp16h(&Bs[(s)*GTILEH + row*RSH + boff],     Bp + (kb)); \
    cp16h(&Bs[(s)*GTILEH + row*RSH + boff + 8], Bp + (kb) + 8); \
} while (0)

    GH_ISSUE(0, 0);  cp_commit();
    GH_ISSUE(32, 1); cp_commit();

    const int nk = DIM / 32;  // 64
    for (int it = 0; it < nk; it++) {
        cp_wait1();
        __syncthreads();
        if (it + 2 < nk) { GH_ISSUE((it + 2) * 32, (it + 2) % GST); }
        cp_commit();

        const uint32_t Ash = As0 + (it % GST) * GTILEH * 2;
        const uint32_t Bsh = Bs0 + (it % GST) * GTILEH * 2;
#pragma unroll
        for (int ks2 = 0; ks2 < 2; ks2++) {
            const int kcol = ks2 * 16 + hi8;
            unsigned af[4][4];
#pragma unroll
            for (int mt = 0; mt < 4; mt++)
                ldm4(af[mt], Ash + ((wm + mt * 16 + ln15) * RSH + kcol) * 2);
#pragma unroll
            for (int p = 0; p < 2; p++) {
                unsigned bq[4];
                ldm4(bq, Bsh + ((wn + p * 16 + ln15) * RSH + kcol) * 2);
#pragma unroll
                for (int sub = 0; sub < 2; sub++) {
                    unsigned bf[2] = { bq[sub], bq[sub + 2] };
#pragma unroll
                    for (int mt = 0; mt < 4; mt++)
                        mma16(acc[mt][p * 2 + sub], af[mt], bf);
                }
            }
        }
    }

#pragma unroll
    for (int mt = 0; mt < 4; mt++) {
        const int m0 = bm + wm + mt * 16 + g;
        const int m1 = m0 + 8;
        size_t ro0, ro1;
        if (!remap) {
            ro0 = (size_t)m0 * DIM; ro1 = (size_t)m1 * DIM;
        } else {
            ro0 = ((size_t)(m0 >> 11) * TTOT + HISTL + (m0 & 2047)) * DIM;
            ro1 = ((size_t)(m1 >> 11) * TTOT + HISTL + (m1 & 2047)) * DIM;
        }
#pragma unroll
        for (int nt = 0; nt < 4; nt++) {
            const int col = bn + wn + nt * 8 + 2 * t;
            *(float2*)&C[ro0 + col] = make_float2(acc[mt][nt][0], acc[mt][nt][1]);
            *(float2*)&C[ro1 + col] = make_float2(acc[mt][nt][2], acc[mt][nt][3]);
            if (CR != nullptr) {
                *(__half2*)&CR[ro0 + col] = __floats2half2_rn(acc[mt][nt][0], acc[mt][nt][1]);
                *(__half2*)&CR[ro1 + col] = __floats2half2_rn(acc[mt][nt][2], acc[mt][nt][3]);
            }
        }
    }
}

// ---------------------------------------------------------------------------
// FP16 flash attention with ldmatrix: BQ=128, warp owns 16 rows.
// ---------------------------------------------------------------------------
#define BQA 128
#define KSH 136
#define VTH 72
#define PSH 72

__global__ __launch_bounds__(256) void attn_f16(
    const float* __restrict__ q, const __half* __restrict__ kh,
    const __half* __restrict__ vt, __half* __restrict__ outp)
{
    extern __shared__ __align__(16) __half smh[];
    __half* K0 = smh;
    __half* K1 = K0 + 64 * KSH;
    __half* V0 = K1 + 64 * KSH;
    __half* V1 = V0 + 128 * VTH;
    __half* Ps = V1 + 128 * VTH;

    const int tid = threadIdx.x, lane = tid & 31, warp = tid >> 5;
    const int g = lane >> 2, t = lane & 3;
    const int ln15 = lane & 15, hi8 = (lane >> 4) * 8;
    const int qt = blockIdx.x, h = blockIdx.y, b = blockIdx.z;
    const int wq = warp * 16;

    const size_t kbase = (size_t)b * TTOT * DIM + h * HD;
    const size_t vbase = ((size_t)b * NHEAD + h) * HD * TTOT;

    const uint32_t K0s = (uint32_t)__cvta_generic_to_shared(K0);
    const uint32_t V0s = (uint32_t)__cvta_generic_to_shared(V0);
    const uint32_t Pss = (uint32_t)__cvta_generic_to_shared(Ps);

#define KV_ISSUE(kt, st) do { \
    __half* Kd = (st) ? K1 : K0; \
    __half* Vd = (st) ? V1 : V0; \
    const size_t kg = kbase + (size_t)((kt) * 64) * DIM; \
    const size_t vg = vbase + (kt) * 64; \
    _Pragma("unroll") \
    for (int i = 0; i < 4; i++) { \
        const int ck = tid + 256 * i; \
        const int kr = ck >> 4, ko = (ck & 15) * 8; \
        cp16h(&Kd[kr * KSH + ko], kh + kg + (size_t)kr * DIM + ko); \
        const int vr = ck >> 3, vo = (ck & 7) * 8; \
        cp16h(&Vd[vr * VTH + vo], vt + vg + (size_t)vr * TTOT + vo); \
    } \
} while (0)

    // Q -> half2 registers
    unsigned qa[8][4];
    {
        const size_t qbase = (size_t)(b * SEQL + qt * BQA + wq) * DIM + h * HD;
        const float* q0 = q + qbase + (size_t)g * DIM;
        const float* q1 = q + qbase + (size_t)(g + 8) * DIM;
#pragma unroll
        for (int kc = 0; kc < 8; kc++) {
            const int k0 = kc * 16 + 2 * t;
            qa[kc][0] = h2u(__floats2half2_rn(q0[k0],     q0[k0 + 1]));
            qa[kc][1] = h2u(__floats2half2_rn(q1[k0],     q1[k0 + 1]));
            qa[kc][2] = h2u(__floats2half2_rn(q0[k0 + 8], q0[k0 + 9]));
            qa[kc][3] = h2u(__floats2half2_rn(q1[k0 + 8], q1[k0 + 9]));
        }
    }

    float O[16][4];
#pragma unroll
    for (int i = 0; i < 16; i++)
#pragma unroll
        for (int c = 0; c < 4; c++) O[i][c] = 0.0f;
    float m0 = -1e30f, m1 = -1e30f, l0 = 0.0f, l1 = 0.0f;

    const int ntiles = HISTL / 64 + 2 * qt + 2;
    const float scale = 0.08838834764831845f;

    KV_ISSUE(0, 0); cp_commit();

    unsigned* Pu = (unsigned*)Ps;

    for (int kt = 0; kt < ntiles; kt++) {
        __syncthreads();
        if (kt + 1 < ntiles) { KV_ISSUE(kt + 1, (kt + 1) & 1); }
        cp_commit();
        cp_wait1();
        __syncthreads();

        const uint32_t Ksh = K0s + (kt & 1) * (64 * KSH * 2);
        const uint32_t Vsh = V0s + (kt & 1) * (128 * VTH * 2);

        // ---- S = Q K^T : 16q x 64kv per warp ----
        float s[8][4];
#pragma unroll
        for (int nt = 0; nt < 8; nt++)
#pragma unroll
            for (int c = 0; c < 4; c++) s[nt][c] = 0.0f;

#pragma unroll
        for (int kc = 0; kc < 8; kc++) {
            const int kcol = kc * 16 + hi8;
#pragma unroll
            for (int p = 0; p < 4; p++) {
                unsigned kq[4];
                ldm4(kq, Ksh + ((p * 16 + ln15) * KSH + kcol) * 2);
#pragma unroll
                for (int sub = 0; sub < 2; sub++) {
                    unsigned bf[2] = { kq[sub], kq[sub + 2] };
                    mma16(s[p * 2 + sub], qa[kc], bf);
                }
            }
        }

        const bool needmask = (kt >= ntiles - 2);
        const int diagoff = HISTL + qt * BQA - kt * 64;
#pragma unroll
        for (int nt = 0; nt < 8; nt++) {
#pragma unroll
            for (int c = 0; c < 4; c++) {
                float v = s[nt][c] * scale;
                if (needmask) {
                    const int rrow = wq + g + ((c >= 2) ? 8 : 0);
                    const int col = nt * 8 + 2 * t + (c & 1);
                    if (col > rrow + diagoff) v = -1e30f;
                }
                s[nt][c] = v;
            }
        }

        float rm0 = -1e30f, rm1 = -1e30f;
#pragma unroll
        for (int nt = 0; nt < 8; nt++) {
            rm0 = fmaxf(rm0, fmaxf(s[nt][0], s[nt][1]));
            rm1 = fmaxf(rm1, fmaxf(s[nt][2], s[nt][3]));
        }
#pragma unroll
        for (int off = 1; off <= 2; off <<= 1) {
            rm0 = fmaxf(rm0, __shfl_xor_sync(0xffffffffu, rm0, off));
            rm1 = fmaxf(rm1, __shfl_xor_sync(0xffffffffu, rm1, off));
        }
        const float mn0 = fmaxf(m0, rm0), mn1 = fmaxf(m1, rm1);
        const float al0 = __expf(m0 - mn0), al1 = __expf(m1 - mn1);

        float rs0 = 0.0f, rs1 = 0.0f;
#pragma unroll
        for (int nt = 0; nt < 8; nt++) {
            float p0 = __expf(s[nt][0] - mn0);
            float p1 = __expf(s[nt][1] - mn0);
            float p2 = __expf(s[nt][2] - mn1);
            float p3 = __expf(s[nt][3] - mn1);
            rs0 += p0 + p1; rs1 += p2 + p3;
            Pu[(wq + g)     * 36 + nt * 4 + t] = h2u(__floats2half2_rn(p0, p1));
            Pu[(wq + g + 8) * 36 + nt * 4 + t] = h2u(__floats2half2_rn(p2, p3));
        }
#pragma unroll
        for (int off = 1; off <= 2; off <<= 1) {
            rs0 += __shfl_xor_sync(0xffffffffu, rs0, off);
            rs1 += __shfl_xor_sync(0xffffffffu, rs1, off);
        }
        l0 = l0 * al0 + rs0;
        l1 = l1 * al1 + rs1;
        m0 = mn0; m1 = mn1;

#pragma unroll
        for (int nt = 0; nt < 16; nt++) {
            O[nt][0] *= al0; O[nt][1] *= al0;
            O[nt][2] *= al1; O[nt][3] *= al1;
        }
        __syncwarp();

        // ---- O += P V : 16q x 128d per warp ----
#pragma unroll
        for (int kc = 0; kc < 4; kc++) {
            const int kcol = kc * 16 + hi8;
            unsigned af[4];
            ldm4(af, Pss + ((wq + ln15) * PSH + kcol) * 2);
#pragma unroll
            for (int p = 0; p < 8; p++) {
                unsigned vq[4];
                ldm4(vq, Vsh + ((p * 16 + ln15) * VTH + kcol) * 2);
#pragma unroll
                for (int sub = 0; sub < 2; sub++) {
                    unsigned bf[2] = { vq[sub], vq[sub + 2] };
                    mma16(O[p * 2 + sub], af, bf);
                }
            }
        }
        __syncwarp();
    }

    const float inv0 = 1.0f / l0, inv1 = 1.0f / l1;
#pragma unroll
    for (int nt = 0; nt < 16; nt++) {
        const int col = h * HD + nt * 8 + 2 * t;
        const size_t r0 = (size_t)(b * SEQL + qt * BQA + wq + g)     * DIM + col;
        const size_t r1 = (size_t)(b * SEQL + qt * BQA + wq + g + 8) * DIM + col;
        *(__half2*)&outp[r0] = __floats2half2_rn(O[nt][0] * inv0, O[nt][1] * inv0);
        *(__half2*)&outp[r1] = __floats2half2_rn(O[nt][2] * inv1, O[nt][3] * inv1);
    }
}

// ---------------------------------------------------------------------------
extern "C" void kernel_launch(void* const* d_in, const int* in_sizes, int n_in,
                              void* d_out, int out_size)
{
    const float* x  = (const float*)d_in[0];
    const float* pk = (const float*)d_in[1];
    const float* pv = (const float*)d_in[2];
    const float* wq = (const float*)d_in[4];
    const float* wk = (const float*)d_in[5];
    const float* wv = (const float*)d_in[6];
    const float* wo = (const float*)d_in[7];

    float* out  = (float*)d_out;
    float* kall = out  + (size_t)BATCH * SEQL * DIM;
    float* vall = kall + (size_t)BATCH * TTOT * DIM;

    float *qbuf; __half *ah, *xh, *wh, *kh, *vt;
    cudaGetSymbolAddress((void**)&qbuf, g_q);
    cudaGetSymbolAddress((void**)&ah,   g_ah);
    cudaGetSymbolAddress((void**)&xh,   g_xh);
    cudaGetSymbolAddress((void**)&wh,   g_wh);
    cudaGetSymbolAddress((void**)&kh,   g_kh);
    cudaGetSymbolAddress((void**)&vt,   g_vt);

    {
        const int tot = 2 * BATCH * HISTL * DIM / 4;
        concat_half_kernel<<<(tot + 255) / 256, 256>>>(pk, pv, kall, vall, kh);
    }
    {
        const int nx4 = MROWS * DIM / 4;
        cvt_f16_kernel<<<(nx4 + 255) / 256, 256>>>(x, xh, nx4);
        const int nwtot = 4 * DIM * DIM / 4;
        cvt_w4_kernel<<<(nwtot + 255) / 256, 256>>>(wq, wk, wv, wo, wh);
    }

    const int gsm = (int)(2u * GST * GTILEH * sizeof(__half));  // 61440
    cudaFuncSetAttribute(gemm_f16, cudaFuncAttributeMaxDynamicSharedMemorySize, gsm);

    dim3 ggrid(DIM / 128, MROWS / 128);
    gemm_f16<<<ggrid, 256, gsm>>>(xh, wh + 0 * (size_t)DIM * DIM, qbuf, nullptr, 0);
    gemm_f16<<<ggrid, 256, gsm>>>(xh, wh + 1 * (size_t)DIM * DIM, kall, kh, 1);
    gemm_f16<<<ggrid, 256, gsm>>>(xh, wh + 2 * (size_t)DIM * DIM, vall, nullptr, 1);

    vtrans_kernel<<<dim3(TTOT / 64, HD / 64, BATCH * NHEAD), 256>>>(vall, vt);

    const int asmh = (int)((2 * 64 * KSH + 2 * 128 * VTH + 128 * PSH) * sizeof(__half));
    cudaFuncSetAttribute(attn_f16, cudaFuncAttributeMaxDynamicSharedMemorySize, asmh);
    attn_f16<<<dim3(SEQL / BQA, NHEAD, BATCH), 256, asmh>>>(qbuf, kh, vt, ah);

    gemm_f16<<<ggrid, 256, gsm>>>(ah, wh + 3 * (size_t)DIM * DIM, out, nullptr, 0);
}